// round 1
// baseline (speedup 1.0000x reference)
#include <cuda_runtime.h>
#include <math.h>

// Problem constants (fixed shapes)
#define S_LEN   2048
#define BATCH   4
#define NHEADS  16
#define DKV     64
#define DMODEL  1024
#define M_ROWS  (BATCH * S_LEN)                 // 8192
#define OUT_ELEMS  (M_ROWS * DMODEL)            // 8388608
#define BIAS_ELEMS (NHEADS * S_LEN * S_LEN)     // 67108864

// Scratch (allowed: __device__ globals)
__device__ float g_q[M_ROWS * DMODEL];
__device__ float g_k[M_ROWS * DMODEL];
__device__ float g_v[M_ROWS * DMODEL];
__device__ float g_attn[M_ROWS * DMODEL];

// ---------------------------------------------------------------------------
// Relative-position bucket, exact integer reformulation of the reference:
//   large = 8 + floor( log(rp/8)/log(16) * 8 ) = 2 + floor(2*log2(rp))
// -> integer thresholds {12,16,23,32,46,64,91}; verified consistent with the
//    f32 reference at all boundary points.
// ---------------------------------------------------------------------------
__device__ __forceinline__ int rel_bucket(int rel) {
    int ret = (rel > 0) ? 16 : 0;
    int rp  = (rel < 0) ? -rel : rel;
    int off;
    if (rp < 8) {
        off = rp;
    } else {
        off = 8 + (rp >= 12) + (rp >= 16) + (rp >= 23) + (rp >= 32)
                + (rp >= 46) + (rp >= 64) + (rp >= 91);
    }
    return ret + off;
}

// ---------------------------------------------------------------------------
// pos_bias writer: bias[h][q][k] = table[bucket(k-q)][h]
// ---------------------------------------------------------------------------
__global__ __launch_bounds__(256) void bias_kernel(const float* __restrict__ tbl,
                                                   float* __restrict__ outb) {
    __shared__ float tcol[32];
    const int q = blockIdx.x;
    const int h = blockIdx.y;
    if (threadIdx.x < 32) tcol[threadIdx.x] = tbl[threadIdx.x * NHEADS + h];
    __syncthreads();
    float* row = outb + ((size_t)h * S_LEN + q) * S_LEN;
    for (int k = threadIdx.x; k < S_LEN; k += 256) {
        row[k] = tcol[rel_bucket(k - q)];
    }
}

// ---------------------------------------------------------------------------
// fp32 SGEMM: C[M,N] = A[M,K] @ B[K,N], 128x128 block, BK=16, 8x8 per thread
// ---------------------------------------------------------------------------
#define BM 128
#define BN 128
#define BK 16

__global__ __launch_bounds__(256, 2) void sgemm128(const float* __restrict__ A,
                                                   const float* __restrict__ B,
                                                   float* __restrict__ C,
                                                   int M, int N, int K) {
    __shared__ float As[BK][BM + 4];   // transposed A tile, padded (stride 132)
    __shared__ float Bs[BK][BN];

    const int tid = threadIdx.x;
    const int tx  = tid & 15;
    const int ty  = tid >> 4;
    const int m0  = blockIdx.y * BM;
    const int n0  = blockIdx.x * BN;

    const int arow = tid >> 2;          // 0..63
    const int acol = (tid & 3) << 2;    // 0,4,8,12
    const int brow = tid >> 5;          // 0..7
    const int bcol = (tid & 31) << 2;   // 0..124

    const float* Ap = A + (size_t)(m0 + arow) * K + acol;
    const float* Bp = B + (size_t)brow * N + n0 + bcol;

    float acc[8][8];
#pragma unroll
    for (int i = 0; i < 8; i++)
#pragma unroll
        for (int j = 0; j < 8; j++) acc[i][j] = 0.0f;

    for (int k0 = 0; k0 < K; k0 += BK) {
        float4 a0 = *(const float4*)Ap;
        float4 a1 = *(const float4*)(Ap + (size_t)64 * K);
        float4 b0 = *(const float4*)Bp;
        float4 b1 = *(const float4*)(Bp + (size_t)8 * N);
        Ap += BK;
        Bp += (size_t)BK * N;

        As[acol + 0][arow]      = a0.x;
        As[acol + 1][arow]      = a0.y;
        As[acol + 2][arow]      = a0.z;
        As[acol + 3][arow]      = a0.w;
        As[acol + 0][arow + 64] = a1.x;
        As[acol + 1][arow + 64] = a1.y;
        As[acol + 2][arow + 64] = a1.z;
        As[acol + 3][arow + 64] = a1.w;
        *(float4*)&Bs[brow][bcol]     = b0;
        *(float4*)&Bs[brow + 8][bcol] = b1;
        __syncthreads();

#pragma unroll
        for (int kk = 0; kk < BK; kk++) {
            float a[8], b[8];
            *(float4*)&a[0] = *(const float4*)&As[kk][ty * 8];
            *(float4*)&a[4] = *(const float4*)&As[kk][ty * 8 + 4];
            *(float4*)&b[0] = *(const float4*)&Bs[kk][tx * 8];
            *(float4*)&b[4] = *(const float4*)&Bs[kk][tx * 8 + 4];
#pragma unroll
            for (int i = 0; i < 8; i++)
#pragma unroll
                for (int j = 0; j < 8; j++)
                    acc[i][j] = fmaf(a[i], b[j], acc[i][j]);
        }
        __syncthreads();
    }

#pragma unroll
    for (int i = 0; i < 8; i++) {
        float* Cp = C + (size_t)(m0 + ty * 8 + i) * N + n0 + tx * 8;
        float4 c0 = make_float4(acc[i][0], acc[i][1], acc[i][2], acc[i][3]);
        float4 c1 = make_float4(acc[i][4], acc[i][5], acc[i][6], acc[i][7]);
        *(float4*)Cp       = c0;
        *(float4*)(Cp + 4) = c1;
    }
}

// ---------------------------------------------------------------------------
// Flash attention (fp32), 64-query x 64-key tiles, bias inline via diag LUT.
// Block: 256 threads (16x16), each thread owns a 4x4 score/output micro-tile.
// ---------------------------------------------------------------------------
#define QPAD 68   // 64 + 4 pad (floats)

__global__ __launch_bounds__(256, 2) void flash_attn(const float* __restrict__ Qg,
                                                     const float* __restrict__ Kg,
                                                     const float* __restrict__ Vg,
                                                     const float* __restrict__ tbl,
                                                     float* __restrict__ Og) {
    extern __shared__ float sm[];
    float* Qs = sm;                 // [64][QPAD]
    float* Ks = Qs + 64 * QPAD;     // [64][QPAD]
    float* Ps = Ks + 64 * QPAD;     // [64][QPAD]  (P transposed: [k][q])
    float* Vs = Ps + 64 * QPAD;     // [64][64]
    __shared__ float tcol[32];
    __shared__ float bdiag[128];

    const int tid = threadIdx.x;
    const int tx  = tid & 15;
    const int ty  = tid >> 4;
    const int q0  = blockIdx.x * 64;
    const int h   = blockIdx.y;
    const int b   = blockIdx.z;

    if (tid < 32) tcol[tid] = tbl[tid * NHEADS + h];

    const float* Qp = Qg + ((size_t)(b * S_LEN + q0)) * DMODEL + h * DKV;
    for (int i = tid; i < 64 * 64; i += 256) {
        int q = i >> 6, d = i & 63;
        Qs[q * QPAD + d] = Qp[(size_t)q * DMODEL + d];
    }

    float o[4][4];
    float mrow[4], lrow[4];
#pragma unroll
    for (int i = 0; i < 4; i++) {
        mrow[i] = -1e30f;
        lrow[i] = 0.0f;
#pragma unroll
        for (int j = 0; j < 4; j++) o[i][j] = 0.0f;
    }

    for (int kt = 0; kt < S_LEN / 64; kt++) {
        const int k0 = kt * 64;
        const float* Kp = Kg + ((size_t)(b * S_LEN + k0)) * DMODEL + h * DKV;
        const float* Vp = Vg + ((size_t)(b * S_LEN + k0)) * DMODEL + h * DKV;

        __syncthreads();  // previous PV done; tcol/Qs ready on first iter
        for (int i = tid; i < 64 * 64; i += 256) {
            int k = i >> 6, d = i & 63;
            Ks[k * QPAD + d] = Kp[(size_t)k * DMODEL + d];
            Vs[k * 64 + d]   = Vp[(size_t)k * DMODEL + d];
        }
        if (tid < 127) {
            int rel = (k0 - q0) + tid - 63;
            bdiag[tid] = tcol[rel_bucket(rel)];
        }
        __syncthreads();

        // S = Q @ K^T  (vectorized over d)
        float s[4][4];
#pragma unroll
        for (int i = 0; i < 4; i++)
#pragma unroll
            for (int j = 0; j < 4; j++) s[i][j] = 0.0f;

#pragma unroll 4
        for (int d4 = 0; d4 < 64; d4 += 4) {
            float4 qf[4], kf[4];
#pragma unroll
            for (int i = 0; i < 4; i++)
                qf[i] = *(const float4*)&Qs[(ty * 4 + i) * QPAD + d4];
#pragma unroll
            for (int j = 0; j < 4; j++)
                kf[j] = *(const float4*)&Ks[(tx * 4 + j) * QPAD + d4];
#pragma unroll
            for (int i = 0; i < 4; i++)
#pragma unroll
                for (int j = 0; j < 4; j++) {
                    s[i][j] = fmaf(qf[i].x, kf[j].x, s[i][j]);
                    s[i][j] = fmaf(qf[i].y, kf[j].y, s[i][j]);
                    s[i][j] = fmaf(qf[i].z, kf[j].z, s[i][j]);
                    s[i][j] = fmaf(qf[i].w, kf[j].w, s[i][j]);
                }
        }

        // bias + online softmax update
#pragma unroll
        for (int i = 0; i < 4; i++) {
#pragma unroll
            for (int j = 0; j < 4; j++)
                s[i][j] += bdiag[(tx * 4 + j) - (ty * 4 + i) + 63];

            float tm = fmaxf(fmaxf(s[i][0], s[i][1]), fmaxf(s[i][2], s[i][3]));
#pragma unroll
            for (int off = 1; off < 16; off <<= 1)
                tm = fmaxf(tm, __shfl_xor_sync(0xffffffffu, tm, off));

            float nm = fmaxf(mrow[i], tm);
            float sc = __expf(mrow[i] - nm);
            mrow[i] = nm;

            float ts = 0.0f;
#pragma unroll
            for (int j = 0; j < 4; j++) {
                float p = __expf(s[i][j] - nm);
                s[i][j] = p;
                ts += p;
            }
#pragma unroll
            for (int off = 1; off < 16; off <<= 1)
                ts += __shfl_xor_sync(0xffffffffu, ts, off);

            lrow[i] = lrow[i] * sc + ts;
#pragma unroll
            for (int j = 0; j < 4; j++) o[i][j] *= sc;
        }

        // store P transposed: Ps[k][q]
#pragma unroll
        for (int i = 0; i < 4; i++)
#pragma unroll
            for (int j = 0; j < 4; j++)
                Ps[(tx * 4 + j) * QPAD + (ty * 4 + i)] = s[i][j];
        __syncthreads();

        // O += P @ V  (vectorized over q via Ps rows, d via Vs rows)
#pragma unroll 8
        for (int k = 0; k < 64; k++) {
            float4 pf = *(const float4*)&Ps[k * QPAD + ty * 4];
            float4 vf = *(const float4*)&Vs[k * 64 + tx * 4];
            o[0][0] = fmaf(pf.x, vf.x, o[0][0]);
            o[0][1] = fmaf(pf.x, vf.y, o[0][1]);
            o[0][2] = fmaf(pf.x, vf.z, o[0][2]);
            o[0][3] = fmaf(pf.x, vf.w, o[0][3]);
            o[1][0] = fmaf(pf.y, vf.x, o[1][0]);
            o[1][1] = fmaf(pf.y, vf.y, o[1][1]);
            o[1][2] = fmaf(pf.y, vf.z, o[1][2]);
            o[1][3] = fmaf(pf.y, vf.w, o[1][3]);
            o[2][0] = fmaf(pf.z, vf.x, o[2][0]);
            o[2][1] = fmaf(pf.z, vf.y, o[2][1]);
            o[2][2] = fmaf(pf.z, vf.z, o[2][2]);
            o[2][3] = fmaf(pf.z, vf.w, o[2][3]);
            o[3][0] = fmaf(pf.w, vf.x, o[3][0]);
            o[3][1] = fmaf(pf.w, vf.y, o[3][1]);
            o[3][2] = fmaf(pf.w, vf.z, o[3][2]);
            o[3][3] = fmaf(pf.w, vf.w, o[3][3]);
        }
    }

    // epilogue: normalize and write [b*S+q][h*64+d]
    float* Op = Og + ((size_t)(b * S_LEN + q0)) * DMODEL + h * DKV;
#pragma unroll
    for (int i = 0; i < 4; i++) {
        float inv = 1.0f / lrow[i];
        float4 r = make_float4(o[i][0] * inv, o[i][1] * inv,
                               o[i][2] * inv, o[i][3] * inv);
        *(float4*)&Op[(size_t)(ty * 4 + i) * DMODEL + tx * 4] = r;
    }
}

// ---------------------------------------------------------------------------
extern "C" void kernel_launch(void* const* d_in, const int* in_sizes, int n_in,
                              void* d_out, int out_size) {
    const float* X   = (const float*)d_in[0];
    const float* Wq  = (const float*)d_in[1];
    const float* Wk  = (const float*)d_in[2];
    const float* Wv  = (const float*)d_in[3];
    const float* Wo  = (const float*)d_in[4];
    const float* tbl = (const float*)d_in[5];
    float* out = (float*)d_out;

    float *dq, *dk, *dv, *da;
    cudaGetSymbolAddress((void**)&dq, g_q);
    cudaGetSymbolAddress((void**)&dk, g_k);
    cudaGetSymbolAddress((void**)&dv, g_v);
    cudaGetSymbolAddress((void**)&da, g_attn);

    // pos_bias (second tuple output), independent of everything else
    if (out_size >= (OUT_ELEMS + BIAS_ELEMS)) {
        dim3 bg(S_LEN, NHEADS);
        bias_kernel<<<bg, 256>>>(tbl, out + OUT_ELEMS);
    }

    dim3 gg(DMODEL / BN, M_ROWS / BM);
    sgemm128<<<gg, 256>>>(X, Wq, dq, M_ROWS, DMODEL, DMODEL);
    sgemm128<<<gg, 256>>>(X, Wk, dk, M_ROWS, DMODEL, DMODEL);
    sgemm128<<<gg, 256>>>(X, Wv, dv, M_ROWS, DMODEL, DMODEL);

    size_t smem = (size_t)(3 * 64 * QPAD + 64 * 64) * sizeof(float);
    cudaFuncSetAttribute(flash_attn, cudaFuncAttributeMaxDynamicSharedMemorySize,
                         (int)smem);
    dim3 fg(S_LEN / 64, NHEADS, BATCH);
    flash_attn<<<fg, 256, smem>>>(dq, dk, dv, tbl, da);

    sgemm128<<<gg, 256>>>(da, Wo, out, M_ROWS, DMODEL, DMODEL);
}

// round 3
// speedup vs baseline: 1.9509x; 1.9509x over previous
#include <cuda_runtime.h>
#include <cuda_bf16.h>
#include <math.h>

// Problem constants (fixed shapes)
#define S_LEN   2048
#define BATCH   4
#define NHEADS  16
#define DKV     64
#define DMODEL  1024
#define M_ROWS  (BATCH * S_LEN)                 // 8192
#define OUT_ELEMS  (M_ROWS * DMODEL)            // 8388608
#define BIAS_ELEMS (NHEADS * S_LEN * S_LEN)     // 67108864

// ---------------------------------------------------------------------------
// Device scratch
// ---------------------------------------------------------------------------
__device__ float g_q[M_ROWS * DMODEL];
__device__ float g_k[M_ROWS * DMODEL];
__device__ float g_v[M_ROWS * DMODEL];
__device__ float g_attn[M_ROWS * DMODEL];
__device__ __nv_bfloat16 g_xh[M_ROWS * DMODEL];
__device__ __nv_bfloat16 g_xl[M_ROWS * DMODEL];
__device__ __nv_bfloat16 g_wqh[DMODEL * DMODEL];
__device__ __nv_bfloat16 g_wql[DMODEL * DMODEL];
__device__ __nv_bfloat16 g_wkh[DMODEL * DMODEL];
__device__ __nv_bfloat16 g_wkl[DMODEL * DMODEL];
__device__ __nv_bfloat16 g_wvh[DMODEL * DMODEL];
__device__ __nv_bfloat16 g_wvl[DMODEL * DMODEL];
__device__ __nv_bfloat16 g_woh[DMODEL * DMODEL];
__device__ __nv_bfloat16 g_wol[DMODEL * DMODEL];

// ---------------------------------------------------------------------------
// PTX helpers (sm_80-level only: mma.sync / ldmatrix / cp.async)
// ---------------------------------------------------------------------------
__device__ __forceinline__ unsigned smem_u32(const void* p) {
    unsigned a;
    asm("{ .reg .u64 t; cvta.to.shared.u64 t, %1; cvt.u32.u64 %0, t; }"
        : "=r"(a) : "l"(p));
    return a;
}

#define LDMATRIX_X4(r0, r1, r2, r3, addr)                                      \
    asm volatile("ldmatrix.sync.aligned.m8n8.x4.shared.b16 {%0,%1,%2,%3}, [%4];" \
                 : "=r"(r0), "=r"(r1), "=r"(r2), "=r"(r3) : "r"(addr))

#define MMA16816(d, a0, a1, a2, a3, b0, b1)                                    \
    asm volatile("mma.sync.aligned.m16n8k16.row.col.f32.bf16.bf16.f32 "        \
                 "{%0,%1,%2,%3},{%4,%5,%6,%7},{%8,%9},{%0,%1,%2,%3};"          \
                 : "+f"((d)[0]), "+f"((d)[1]), "+f"((d)[2]), "+f"((d)[3])      \
                 : "r"(a0), "r"(a1), "r"(a2), "r"(a3), "r"(b0), "r"(b1))

#define CP_ASYNC16(dst, src)                                                   \
    asm volatile("cp.async.cg.shared.global [%0], [%1], 16;"                   \
                 :: "r"(dst), "l"(src) : "memory")
#define CP_COMMIT() asm volatile("cp.async.commit_group;" ::: "memory")
#define CP_WAIT1()  asm volatile("cp.async.wait_group 1;" ::: "memory")

// ---------------------------------------------------------------------------
// Relative-position bucket (exact integer reformulation of the reference)
// ---------------------------------------------------------------------------
__device__ __forceinline__ int rel_bucket(int rel) {
    int ret = (rel > 0) ? 16 : 0;
    int rp  = (rel < 0) ? -rel : rel;
    int off;
    if (rp < 8) {
        off = rp;
    } else {
        off = 8 + (rp >= 12) + (rp >= 16) + (rp >= 23) + (rp >= 32)
                + (rp >= 46) + (rp >= 64) + (rp >= 91);
    }
    return ret + off;
}

// ---------------------------------------------------------------------------
// pos_bias writer
// ---------------------------------------------------------------------------
__global__ __launch_bounds__(256) void bias_kernel(const float* __restrict__ tbl,
                                                   float* __restrict__ outb) {
    __shared__ float tcol[32];
    const int q = blockIdx.x;
    const int h = blockIdx.y;
    if (threadIdx.x < 32) tcol[threadIdx.x] = tbl[threadIdx.x * NHEADS + h];
    __syncthreads();
    float* row = outb + ((size_t)h * S_LEN + q) * S_LEN;
    for (int k = threadIdx.x; k < S_LEN; k += 256) {
        row[k] = tcol[rel_bucket(k - q)];
    }
}

// ---------------------------------------------------------------------------
// f32 -> bf16 hi/lo split (elementwise, float4)
// ---------------------------------------------------------------------------
__global__ __launch_bounds__(256) void split_kernel(const float* __restrict__ in,
                                                    __nv_bfloat16* __restrict__ hi,
                                                    __nv_bfloat16* __restrict__ lo,
                                                    int n4) {
    int idx = blockIdx.x * 256 + threadIdx.x;
    if (idx >= n4) return;
    float4 v = ((const float4*)in)[idx];
    __nv_bfloat16 h0 = __float2bfloat16(v.x);
    __nv_bfloat16 h1 = __float2bfloat16(v.y);
    __nv_bfloat16 h2 = __float2bfloat16(v.z);
    __nv_bfloat16 h3 = __float2bfloat16(v.w);
    __nv_bfloat16 l0 = __float2bfloat16(v.x - __bfloat162float(h0));
    __nv_bfloat16 l1 = __float2bfloat16(v.y - __bfloat162float(h1));
    __nv_bfloat16 l2 = __float2bfloat16(v.z - __bfloat162float(h2));
    __nv_bfloat16 l3 = __float2bfloat16(v.w - __bfloat162float(h3));
    __nv_bfloat162* H = (__nv_bfloat162*)hi;
    __nv_bfloat162* L = (__nv_bfloat162*)lo;
    H[idx * 2]     = __nv_bfloat162(h0, h1);
    H[idx * 2 + 1] = __nv_bfloat162(h2, h3);
    L[idx * 2]     = __nv_bfloat162(l0, l1);
    L[idx * 2 + 1] = __nv_bfloat162(l2, l3);
}

// ---------------------------------------------------------------------------
// 1024x1024 transpose + hi/lo split:  out[n][k] = W[k][n]
// ---------------------------------------------------------------------------
__global__ __launch_bounds__(256) void transpose_split(const float* __restrict__ W,
                                                       __nv_bfloat16* __restrict__ Th,
                                                       __nv_bfloat16* __restrict__ Tl) {
    __shared__ float t[32][33];
    const int tx = threadIdx.x, ty = threadIdx.y;
    const int nb = blockIdx.x * 32, kb = blockIdx.y * 32;
#pragma unroll
    for (int r = ty; r < 32; r += 8)
        t[r][tx] = W[(size_t)(kb + r) * DMODEL + nb + tx];
    __syncthreads();
#pragma unroll
    for (int r = ty; r < 32; r += 8) {
        float v = t[tx][r];  // = W[kb+tx][nb+r]
        __nv_bfloat16 h = __float2bfloat16(v);
        Th[(size_t)(nb + r) * DMODEL + kb + tx] = h;
        Tl[(size_t)(nb + r) * DMODEL + kb + tx] =
            __float2bfloat16(v - __bfloat162float(h));
    }
}

// ---------------------------------------------------------------------------
// HMMA split-bf16 GEMM:  C[M,N] = (Ah+Al)[M,K] @ (Bh+Bl)[N,K]^T
// 128x128 CTA tile, BK=32, 8 warps @ 64x32, 3-stage cp.async pipeline.
// smem rows padded to 80B (20 words): conflict-free ldmatrix.
// ---------------------------------------------------------------------------
#define GSTAGES 3
#define ROWB 80                               // bytes per smem row (32 bf16 + pad)
#define MATB (128 * ROWB)                     // 10240 B per matrix tile
#define STAGEB (4 * MATB)                     // Ah, Al, Bh, Bl
#define GEMM_SMEM (GSTAGES * STAGEB)          // 122880 B

__global__ __launch_bounds__(256, 1)
void gemm_mma(const __nv_bfloat16* __restrict__ Ah,
              const __nv_bfloat16* __restrict__ Al,
              const __nv_bfloat16* __restrict__ Bh,
              const __nv_bfloat16* __restrict__ Bl,
              float* __restrict__ C, int M, int N, int K) {
    extern __shared__ char smx[];
    const unsigned sb = smem_u32(smx);
    const int tid  = threadIdx.x;
    const int wid  = tid >> 5;
    const int lane = tid & 31;
    const int m0 = blockIdx.y * 128, n0 = blockIdx.x * 128;
    const int wm = (wid & 1) * 64;            // warp row offset in tile
    const int wn = (wid >> 1) * 32;           // warp col offset in tile

    const __nv_bfloat16* src0 = Ah + (size_t)m0 * K;
    const __nv_bfloat16* src1 = Al + (size_t)m0 * K;
    const __nv_bfloat16* src2 = Bh + (size_t)n0 * K;
    const __nv_bfloat16* src3 = Bl + (size_t)n0 * K;

    const int ldrow = tid >> 2;               // 0..63 (row pair base)
    const int ldch  = tid & 3;                // 16B chunk within 32-elem row

    // ldmatrix lane addressing (within a 128xROWB matrix tile)
    const unsigned a_off = (unsigned)((lane & 15) * ROWB + (lane >> 4) * 16);
    const unsigned b_off = (unsigned)((((lane >> 4) << 3) + (lane & 7)) * ROWB
                                      + ((lane >> 3) & 1) * 16);

    float acc[4][4][4];
#pragma unroll
    for (int i = 0; i < 4; i++)
#pragma unroll
        for (int j = 0; j < 4; j++)
#pragma unroll
            for (int r = 0; r < 4; r++) acc[i][j][r] = 0.0f;

    const int NIT = K / 32;

    // ---- pipelined loads ----
    auto load_stage = [&](int s, int kit) {
        const int k0 = kit * 32;
        unsigned dbase = sb + (unsigned)(s * STAGEB);
        const __nv_bfloat16* gsrc[4] = {src0 + k0, src1 + k0, src2 + k0, src3 + k0};
#pragma unroll
        for (int mtx = 0; mtx < 4; mtx++) {
#pragma unroll
            for (int i = 0; i < 2; i++) {
                int row = ldrow + i * 64;
                unsigned dst = dbase + (unsigned)(mtx * MATB + row * ROWB + ldch * 16);
                const char* src = (const char*)(gsrc[mtx] + (size_t)row * K) + ldch * 16;
                CP_ASYNC16(dst, src);
            }
        }
    };

#pragma unroll
    for (int s = 0; s < GSTAGES - 1; s++) {
        load_stage(s, s);
        CP_COMMIT();
    }

    for (int kit = 0; kit < NIT; kit++) {
        CP_WAIT1();
        __syncthreads();
        if (kit + GSTAGES - 1 < NIT) load_stage((kit + GSTAGES - 1) % GSTAGES,
                                                kit + GSTAGES - 1);
        CP_COMMIT();

        const unsigned tb = sb + (unsigned)((kit % GSTAGES) * STAGEB);
#pragma unroll
        for (int kk = 0; kk < 32; kk += 16) {
            unsigned afr[2][4][4];   // [split][m-tile][reg]
            unsigned bfr[2][2][4];   // [split][n16-pair][reg]
#pragma unroll
            for (int sp = 0; sp < 2; sp++) {
#pragma unroll
                for (int mt = 0; mt < 4; mt++) {
                    unsigned ad = tb + (unsigned)(sp * MATB) + a_off
                                + (unsigned)((wm + mt * 16) * ROWB + kk * 2);
                    LDMATRIX_X4(afr[sp][mt][0], afr[sp][mt][1],
                                afr[sp][mt][2], afr[sp][mt][3], ad);
                }
#pragma unroll
                for (int nt = 0; nt < 2; nt++) {
                    unsigned bd = tb + (unsigned)((2 + sp) * MATB) + b_off
                                + (unsigned)((wn + nt * 16) * ROWB + kk * 2);
                    LDMATRIX_X4(bfr[sp][nt][0], bfr[sp][nt][1],
                                bfr[sp][nt][2], bfr[sp][nt][3], bd);
                }
            }
#pragma unroll
            for (int mt = 0; mt < 4; mt++) {
#pragma unroll
                for (int nt = 0; nt < 4; nt++) {
                    const int pr = nt >> 1, hf = (nt & 1) * 2;
                    unsigned bh0 = bfr[0][pr][hf], bh1 = bfr[0][pr][hf + 1];
                    unsigned bl0 = bfr[1][pr][hf], bl1 = bfr[1][pr][hf + 1];
                    MMA16816(acc[mt][nt], afr[0][mt][0], afr[0][mt][1],
                             afr[0][mt][2], afr[0][mt][3], bh0, bh1);
                    MMA16816(acc[mt][nt], afr[0][mt][0], afr[0][mt][1],
                             afr[0][mt][2], afr[0][mt][3], bl0, bl1);
                    MMA16816(acc[mt][nt], afr[1][mt][0], afr[1][mt][1],
                             afr[1][mt][2], afr[1][mt][3], bh0, bh1);
                }
            }
        }
        __syncthreads();
    }

    // ---- epilogue ----
    const int r0 = lane >> 2, c0 = (lane & 3) * 2;
#pragma unroll
    for (int mt = 0; mt < 4; mt++) {
#pragma unroll
        for (int nt = 0; nt < 4; nt++) {
            int row = m0 + wm + mt * 16 + r0;
            int col = n0 + wn + nt * 8 + c0;
            float* Cp = C + (size_t)row * N + col;
            *(float2*)Cp = make_float2(acc[mt][nt][0], acc[mt][nt][1]);
            *(float2*)(Cp + (size_t)8 * N) = make_float2(acc[mt][nt][2], acc[mt][nt][3]);
        }
    }
}

// ---------------------------------------------------------------------------
// Flash attention (fp32): 128q x 128k tiles, 256 threads, 8x8 micro-tiles.
// Ks uses per-row XOR chunk swizzle; P stored [q][k] (broadcast PV reads).
// ---------------------------------------------------------------------------
#define FLASH_SMEM ((128 * 64 * 3 + 128 * 128) * 4)

__global__ __launch_bounds__(256, 1) void flash_attn2(const float* __restrict__ Qg,
                                                      const float* __restrict__ Kg,
                                                      const float* __restrict__ Vg,
                                                      const float* __restrict__ tbl,
                                                      float* __restrict__ Og) {
    extern __shared__ float sm[];
    float* Qs = sm;                  // [128][64]
    float* Ks = Qs + 128 * 64;       // [128][64], XOR-swizzled 16B chunks
    float* Vs = Ks + 128 * 64;       // [128][64]
    float* Ps = Vs + 128 * 64;       // [128][128]
    __shared__ float tcol[32];
    __shared__ float bdiag[256];

    const int tid = threadIdx.x;
    const int tx  = tid & 15;        // k / d groups
    const int ty  = tid >> 4;        // q groups
    const int q0  = blockIdx.x * 128;
    const int h   = blockIdx.y;
    const int b   = blockIdx.z;

    if (tid < 32) tcol[tid] = tbl[tid * NHEADS + h];

    const float* Qp = Qg + ((size_t)(b * S_LEN + q0)) * DMODEL + h * DKV;
    for (int i = tid; i < 128 * 16; i += 256) {
        int q = i >> 4, c = i & 15;
        *(float4*)&Qs[q * 64 + c * 4] = *(const float4*)&Qp[(size_t)q * DMODEL + c * 4];
    }

    float o[8][4];
    float mrow[8], lrow[8];
#pragma unroll
    for (int i = 0; i < 8; i++) {
        mrow[i] = -1e30f; lrow[i] = 0.0f;
#pragma unroll
        for (int j = 0; j < 4; j++) o[i][j] = 0.0f;
    }

    for (int kt = 0; kt < S_LEN / 128; kt++) {
        const int k0 = kt * 128;
        const float* Kp = Kg + ((size_t)(b * S_LEN + k0)) * DMODEL + h * DKV;
        const float* Vp = Vg + ((size_t)(b * S_LEN + k0)) * DMODEL + h * DKV;

        __syncthreads();  // previous PV done (and Qs/tcol ready on iter 0)
        for (int i = tid; i < 128 * 16; i += 256) {
            int k = i >> 4, c = i & 15;
            float4 kv = *(const float4*)&Kp[(size_t)k * DMODEL + c * 4];
            float4 vv = *(const float4*)&Vp[(size_t)k * DMODEL + c * 4];
            int csw = c ^ ((k >> 3) & 7);
            *(float4*)&Ks[k * 64 + csw * 4] = kv;
            *(float4*)&Vs[k * 64 + c * 4]   = vv;
        }
        if (tid < 255) bdiag[tid] = tcol[rel_bucket(k0 - q0 + tid - 127)];
        __syncthreads();

        // S = Q @ K^T
        float s[8][8];
#pragma unroll
        for (int i = 0; i < 8; i++)
#pragma unroll
            for (int j = 0; j < 8; j++) s[i][j] = 0.0f;

        for (int d4 = 0; d4 < 64; d4 += 4) {
            const int csw = ((d4 >> 2) ^ (tx & 7)) << 2;
            float4 kf[8];
#pragma unroll
            for (int j = 0; j < 8; j++)
                kf[j] = *(const float4*)&Ks[(tx * 8 + j) * 64 + csw];
#pragma unroll
            for (int i = 0; i < 8; i++) {
                float4 qf = *(const float4*)&Qs[(ty * 8 + i) * 64 + d4];
#pragma unroll
                for (int j = 0; j < 8; j++) {
                    s[i][j] = fmaf(qf.x, kf[j].x, s[i][j]);
                    s[i][j] = fmaf(qf.y, kf[j].y, s[i][j]);
                    s[i][j] = fmaf(qf.z, kf[j].z, s[i][j]);
                    s[i][j] = fmaf(qf.w, kf[j].w, s[i][j]);
                }
            }
        }

        // bias + online softmax, write P [q][k]
#pragma unroll
        for (int i = 0; i < 8; i++) {
            const int qq = ty * 8 + i;
#pragma unroll
            for (int j = 0; j < 8; j++)
                s[i][j] += bdiag[(tx * 8 + j) - qq + 127];

            float tm = s[i][0];
#pragma unroll
            for (int j = 1; j < 8; j++) tm = fmaxf(tm, s[i][j]);
#pragma unroll
            for (int off = 1; off < 16; off <<= 1)
                tm = fmaxf(tm, __shfl_xor_sync(0xffffffffu, tm, off));

            float nm = fmaxf(mrow[i], tm);
            float sc = __expf(mrow[i] - nm);
            mrow[i] = nm;

            float ts = 0.0f;
#pragma unroll
            for (int j = 0; j < 8; j++) {
                float p = __expf(s[i][j] - nm);
                s[i][j] = p;
                ts += p;
            }
#pragma unroll
            for (int off = 1; off < 16; off <<= 1)
                ts += __shfl_xor_sync(0xffffffffu, ts, off);

            lrow[i] = lrow[i] * sc + ts;
#pragma unroll
            for (int j = 0; j < 4; j++) o[i][j] *= sc;

            *(float4*)&Ps[qq * 128 + tx * 8] =
                make_float4(s[i][0], s[i][1], s[i][2], s[i][3]);
            *(float4*)&Ps[qq * 128 + tx * 8 + 4] =
                make_float4(s[i][4], s[i][5], s[i][6], s[i][7]);
        }
        __syncthreads();

        // O += P @ V : thread covers 8 q-rows x 4 d-cols (d = tx*4..)
        for (int k4 = 0; k4 < 128; k4 += 4) {
            float4 vf[4];
#pragma unroll
            for (int r = 0; r < 4; r++)
                vf[r] = *(const float4*)&Vs[(k4 + r) * 64 + tx * 4];
#pragma unroll
            for (int i = 0; i < 8; i++) {
                float4 pf = *(const float4*)&Ps[(ty * 8 + i) * 128 + k4];
                o[i][0] = fmaf(pf.x, vf[0].x, o[i][0]);
                o[i][1] = fmaf(pf.x, vf[0].y, o[i][1]);
                o[i][2] = fmaf(pf.x, vf[0].z, o[i][2]);
                o[i][3] = fmaf(pf.x, vf[0].w, o[i][3]);
                o[i][0] = fmaf(pf.y, vf[1].x, o[i][0]);
                o[i][1] = fmaf(pf.y, vf[1].y, o[i][1]);
                o[i][2] = fmaf(pf.y, vf[1].z, o[i][2]);
                o[i][3] = fmaf(pf.y, vf[1].w, o[i][3]);
                o[i][0] = fmaf(pf.z, vf[2].x, o[i][0]);
                o[i][1] = fmaf(pf.z, vf[2].y, o[i][1]);
                o[i][2] = fmaf(pf.z, vf[2].z, o[i][2]);
                o[i][3] = fmaf(pf.z, vf[2].w, o[i][3]);
                o[i][0] = fmaf(pf.w, vf[3].x, o[i][0]);
                o[i][1] = fmaf(pf.w, vf[3].y, o[i][1]);
                o[i][2] = fmaf(pf.w, vf[3].z, o[i][2]);
                o[i][3] = fmaf(pf.w, vf[3].w, o[i][3]);
            }
        }
    }

    // epilogue
    float* Op = Og + ((size_t)(b * S_LEN + q0)) * DMODEL + h * DKV;
#pragma unroll
    for (int i = 0; i < 8; i++) {
        float inv = 1.0f / lrow[i];
        float4 r = make_float4(o[i][0] * inv, o[i][1] * inv,
                               o[i][2] * inv, o[i][3] * inv);
        *(float4*)&Op[(size_t)(ty * 8 + i) * DMODEL + tx * 4] = r;
    }
}

// ---------------------------------------------------------------------------
extern "C" void kernel_launch(void* const* d_in, const int* in_sizes, int n_in,
                              void* d_out, int out_size) {
    const float* X   = (const float*)d_in[0];
    const float* Wq  = (const float*)d_in[1];
    const float* Wk  = (const float*)d_in[2];
    const float* Wv  = (const float*)d_in[3];
    const float* Wo  = (const float*)d_in[4];
    const float* tbl = (const float*)d_in[5];
    float* out = (float*)d_out;

    float *dq, *dk, *dv, *da;
    __nv_bfloat16 *xh, *xl, *wqh, *wql, *wkh, *wkl, *wvh, *wvl, *woh, *wol;
    cudaGetSymbolAddress((void**)&dq, g_q);
    cudaGetSymbolAddress((void**)&dk, g_k);
    cudaGetSymbolAddress((void**)&dv, g_v);
    cudaGetSymbolAddress((void**)&da, g_attn);
    cudaGetSymbolAddress((void**)&xh, g_xh);
    cudaGetSymbolAddress((void**)&xl, g_xl);
    cudaGetSymbolAddress((void**)&wqh, g_wqh);
    cudaGetSymbolAddress((void**)&wql, g_wql);
    cudaGetSymbolAddress((void**)&wkh, g_wkh);
    cudaGetSymbolAddress((void**)&wkl, g_wkl);
    cudaGetSymbolAddress((void**)&wvh, g_wvh);
    cudaGetSymbolAddress((void**)&wvl, g_wvl);
    cudaGetSymbolAddress((void**)&woh, g_woh);
    cudaGetSymbolAddress((void**)&wol, g_wol);

    // pos_bias (independent)
    {
        dim3 bg(S_LEN, NHEADS);
        bias_kernel<<<bg, 256>>>(tbl, out + OUT_ELEMS);
    }

    // conversions
    {
        int n4 = OUT_ELEMS / 4;
        split_kernel<<<(n4 + 255) / 256, 256>>>(X, xh, xl, n4);
        dim3 tb(32, 8), tg(32, 32);
        transpose_split<<<tg, tb>>>(Wq, wqh, wql);
        transpose_split<<<tg, tb>>>(Wk, wkh, wkl);
        transpose_split<<<tg, tb>>>(Wv, wvh, wvl);
        transpose_split<<<tg, tb>>>(Wo, woh, wol);
    }

    cudaFuncSetAttribute(gemm_mma, cudaFuncAttributeMaxDynamicSharedMemorySize,
                         GEMM_SMEM);
    dim3 gg(DMODEL / 128, M_ROWS / 128);
    gemm_mma<<<gg, 256, GEMM_SMEM>>>(xh, xl, wqh, wql, dq, M_ROWS, DMODEL, DMODEL);
    gemm_mma<<<gg, 256, GEMM_SMEM>>>(xh, xl, wkh, wkl, dk, M_ROWS, DMODEL, DMODEL);
    gemm_mma<<<gg, 256, GEMM_SMEM>>>(xh, xl, wvh, wvl, dv, M_ROWS, DMODEL, DMODEL);

    cudaFuncSetAttribute(flash_attn2, cudaFuncAttributeMaxDynamicSharedMemorySize,
                         FLASH_SMEM);
    dim3 fg(S_LEN / 128, NHEADS, BATCH);
    flash_attn2<<<fg, 256, FLASH_SMEM>>>(dq, dk, dv, tbl, da);

    // output projection: split attn output, then GEMM into d_out
    {
        int n4 = OUT_ELEMS / 4;
        split_kernel<<<(n4 + 255) / 256, 256>>>(da, xh, xl, n4);
    }
    gemm_mma<<<gg, 256, GEMM_SMEM>>>(xh, xl, woh, wol, out, M_ROWS, DMODEL, DMODEL);
}

// round 4
// speedup vs baseline: 4.5949x; 2.3553x over previous
#include <cuda_runtime.h>
#include <cuda_fp16.h>
#include <math.h>

// Problem constants (fixed shapes)
#define S_LEN   2048
#define BATCH   4
#define NHEADS  16
#define DKV     64
#define DMODEL  1024
#define M_ROWS  (BATCH * S_LEN)                 // 8192
#define OUT_ELEMS  (M_ROWS * DMODEL)            // 8388608
#define BIAS_ELEMS (NHEADS * S_LEN * S_LEN)     // 67108864

// ---------------------------------------------------------------------------
// Device scratch (fp16 everywhere)
// ---------------------------------------------------------------------------
__device__ __half g_xh[M_ROWS * DMODEL];
__device__ __half g_xl[M_ROWS * DMODEL];
__device__ __half g_wqh[DMODEL * DMODEL];
__device__ __half g_wql[DMODEL * DMODEL];
__device__ __half g_wkh[DMODEL * DMODEL];
__device__ __half g_wkl[DMODEL * DMODEL];
__device__ __half g_wvh[DMODEL * DMODEL];
__device__ __half g_wvl[DMODEL * DMODEL];
__device__ __half g_woh[DMODEL * DMODEL];
__device__ __half g_wol[DMODEL * DMODEL];
__device__ __half g_qh[M_ROWS * DMODEL];
__device__ __half g_ql[M_ROWS * DMODEL];
__device__ __half g_kh[M_ROWS * DMODEL];
__device__ __half g_kl[M_ROWS * DMODEL];
__device__ __half g_vh[M_ROWS * DMODEL];
__device__ __half g_oh[M_ROWS * DMODEL];

// ---------------------------------------------------------------------------
// PTX helpers (sm_80-level only)
// ---------------------------------------------------------------------------
__device__ __forceinline__ unsigned smem_u32(const void* p) {
    unsigned a;
    asm("{ .reg .u64 t; cvta.to.shared.u64 t, %1; cvt.u32.u64 %0, t; }"
        : "=r"(a) : "l"(p));
    return a;
}

#define LDMATRIX_X4(r0, r1, r2, r3, addr)                                      \
    asm volatile("ldmatrix.sync.aligned.m8n8.x4.shared.b16 {%0,%1,%2,%3}, [%4];" \
                 : "=r"(r0), "=r"(r1), "=r"(r2), "=r"(r3) : "r"(addr))

#define LDMATRIX_X4_T(r0, r1, r2, r3, addr)                                    \
    asm volatile("ldmatrix.sync.aligned.m8n8.x4.trans.shared.b16 {%0,%1,%2,%3}, [%4];" \
                 : "=r"(r0), "=r"(r1), "=r"(r2), "=r"(r3) : "r"(addr))

#define MMAF16(d, a0, a1, a2, a3, b0, b1)                                      \
    asm volatile("mma.sync.aligned.m16n8k16.row.col.f32.f16.f16.f32 "          \
                 "{%0,%1,%2,%3},{%4,%5,%6,%7},{%8,%9},{%0,%1,%2,%3};"          \
                 : "+f"((d)[0]), "+f"((d)[1]), "+f"((d)[2]), "+f"((d)[3])      \
                 : "r"(a0), "r"(a1), "r"(a2), "r"(a3), "r"(b0), "r"(b1))

#define CP_ASYNC16(dst, src)                                                   \
    asm volatile("cp.async.cg.shared.global [%0], [%1], 16;"                   \
                 :: "r"(dst), "l"(src) : "memory")
#define CP_COMMIT() asm volatile("cp.async.commit_group;" ::: "memory")
#define CP_WAIT1()  asm volatile("cp.async.wait_group 1;" ::: "memory")
#define CP_WAIT0()  asm volatile("cp.async.wait_group 0;" ::: "memory")

__device__ __forceinline__ unsigned pack2h(float a, float b) {
    __half2 h = __floats2half2_rn(a, b);
    return *reinterpret_cast<unsigned*>(&h);
}

// ---------------------------------------------------------------------------
// Relative-position bucket (exact integer reformulation of the reference)
// ---------------------------------------------------------------------------
__device__ __forceinline__ int rel_bucket(int rel) {
    int ret = (rel > 0) ? 16 : 0;
    int rp  = (rel < 0) ? -rel : rel;
    int off;
    if (rp < 8) {
        off = rp;
    } else {
        off = 8 + (rp >= 12) + (rp >= 16) + (rp >= 23) + (rp >= 32)
                + (rp >= 46) + (rp >= 64) + (rp >= 91);
    }
    return ret + off;
}

// ---------------------------------------------------------------------------
// pos_bias writer
// ---------------------------------------------------------------------------
__global__ __launch_bounds__(256) void bias_kernel(const float* __restrict__ tbl,
                                                   float* __restrict__ outb) {
    __shared__ float tcol[32];
    const int q = blockIdx.x;
    const int h = blockIdx.y;
    if (threadIdx.x < 32) tcol[threadIdx.x] = tbl[threadIdx.x * NHEADS + h];
    __syncthreads();
    float* row = outb + ((size_t)h * S_LEN + q) * S_LEN;
    for (int k = threadIdx.x; k < S_LEN; k += 256) {
        row[k] = tcol[rel_bucket(k - q)];
    }
}

// ---------------------------------------------------------------------------
// f32 -> fp16 hi/lo split (elementwise, float4)
// ---------------------------------------------------------------------------
__global__ __launch_bounds__(256) void split_kernel(const float* __restrict__ in,
                                                    __half* __restrict__ hi,
                                                    __half* __restrict__ lo,
                                                    int n4) {
    int idx = blockIdx.x * 256 + threadIdx.x;
    if (idx >= n4) return;
    float4 v = ((const float4*)in)[idx];
    __half h0 = __float2half_rn(v.x), h1 = __float2half_rn(v.y);
    __half h2 = __float2half_rn(v.z), h3 = __float2half_rn(v.w);
    unsigned* H = (unsigned*)hi;
    unsigned* L = (unsigned*)lo;
    H[idx * 2]     = pack2h(v.x, v.y);
    H[idx * 2 + 1] = pack2h(v.z, v.w);
    L[idx * 2]     = pack2h(v.x - __half2float(h0), v.y - __half2float(h1));
    L[idx * 2 + 1] = pack2h(v.z - __half2float(h2), v.w - __half2float(h3));
}

// ---------------------------------------------------------------------------
// 1024x1024 transpose + fp16 hi/lo split:  out[n][k] = W[k][n]
// ---------------------------------------------------------------------------
__global__ __launch_bounds__(256) void transpose_split(const float* __restrict__ W,
                                                       __half* __restrict__ Th,
                                                       __half* __restrict__ Tl) {
    __shared__ float t[32][33];
    const int tx = threadIdx.x, ty = threadIdx.y;
    const int nb = blockIdx.x * 32, kb = blockIdx.y * 32;
#pragma unroll
    for (int r = ty; r < 32; r += 8)
        t[r][tx] = W[(size_t)(kb + r) * DMODEL + nb + tx];
    __syncthreads();
#pragma unroll
    for (int r = ty; r < 32; r += 8) {
        float v = t[tx][r];  // = W[kb+tx][nb+r]
        __half h = __float2half_rn(v);
        Th[(size_t)(nb + r) * DMODEL + kb + tx] = h;
        Tl[(size_t)(nb + r) * DMODEL + kb + tx] =
            __float2half_rn(v - __half2float(h));
    }
}

// ---------------------------------------------------------------------------
// HMMA fp16 GEMM, templated:
//   SPLIT==3: C = AhBh + AhBl + AlBh  (hi/lo compensated, ~fp32 quality)
//   SPLIT==1: C = AhBh               (single-pass fp16)
//   OUTM: 0 -> float C; 1 -> fp16 hi/lo pair; 2 -> fp16 single
// 128x128 CTA tile, BK=32, 8 warps @ 64x32, 3-stage cp.async pipeline.
// ---------------------------------------------------------------------------
#define GSTAGES 3
#define ROWB 80                               // 32 fp16 (64B) + 16B pad
#define MATB (128 * ROWB)                     // 10240 B

template<int SPLIT, int OUTM>
__global__ __launch_bounds__(256, 1)
void gemm_h(const __half* __restrict__ Ah, const __half* __restrict__ Al,
            const __half* __restrict__ Bh, const __half* __restrict__ Bl,
            float* __restrict__ Cf, __half* __restrict__ Ch,
            __half* __restrict__ Cl, int M, int N, int K) {
    constexpr int NMATS = (SPLIT == 3) ? 4 : 2;
    constexpr int STAGEB = NMATS * MATB;
    extern __shared__ char smx[];
    const unsigned sb = smem_u32(smx);
    const int tid  = threadIdx.x;
    const int wid  = tid >> 5;
    const int lane = tid & 31;
    const int m0 = blockIdx.y * 128, n0 = blockIdx.x * 128;
    const int wm = (wid & 1) * 64;
    const int wn = (wid >> 1) * 32;

    // mat order: 0=Ah, 1=Bh, 2=Al, 3=Bl
    const __half* srcs[4];
    srcs[0] = Ah + (size_t)m0 * K;
    srcs[1] = Bh + (size_t)n0 * K;
    srcs[2] = Al + (size_t)m0 * K;
    srcs[3] = Bl + (size_t)n0 * K;

    const int ldrow = tid >> 2;
    const int ldch  = tid & 3;

    const unsigned a_off = (unsigned)((lane & 15) * ROWB + (lane >> 4) * 16);
    const unsigned b_off = (unsigned)((((lane >> 4) << 3) + (lane & 7)) * ROWB
                                      + ((lane >> 3) & 1) * 16);

    float acc[4][4][4];
#pragma unroll
    for (int i = 0; i < 4; i++)
#pragma unroll
        for (int j = 0; j < 4; j++)
#pragma unroll
            for (int r = 0; r < 4; r++) acc[i][j][r] = 0.0f;

    const int NIT = K / 32;

    auto load_stage = [&](int s, int kit) {
        const int k0 = kit * 32;
        unsigned dbase = sb + (unsigned)(s * STAGEB);
#pragma unroll
        for (int mtx = 0; mtx < NMATS; mtx++) {
#pragma unroll
            for (int i = 0; i < 2; i++) {
                int row = ldrow + i * 64;
                unsigned dst = dbase + (unsigned)(mtx * MATB + row * ROWB + ldch * 16);
                const char* src = (const char*)(srcs[mtx] + k0 + (size_t)row * K)
                                + ldch * 16;
                CP_ASYNC16(dst, src);
            }
        }
    };

#pragma unroll
    for (int s = 0; s < GSTAGES - 1; s++) {
        load_stage(s, s);
        CP_COMMIT();
    }

    for (int kit = 0; kit < NIT; kit++) {
        CP_WAIT1();
        __syncthreads();
        if (kit + GSTAGES - 1 < NIT) load_stage((kit + GSTAGES - 1) % GSTAGES,
                                                kit + GSTAGES - 1);
        CP_COMMIT();

        const unsigned tb = sb + (unsigned)((kit % GSTAGES) * STAGEB);
#pragma unroll
        for (int kk = 0; kk < 32; kk += 16) {
            unsigned afr[2][4][4];
            unsigned bfr[2][2][4];
            const int NSP = (SPLIT == 3) ? 2 : 1;
#pragma unroll
            for (int sp = 0; sp < NSP; sp++) {
#pragma unroll
                for (int mt = 0; mt < 4; mt++) {
                    unsigned ad = tb + (unsigned)(sp * 2 * MATB) + a_off
                                + (unsigned)((wm + mt * 16) * ROWB + kk * 2);
                    LDMATRIX_X4(afr[sp][mt][0], afr[sp][mt][1],
                                afr[sp][mt][2], afr[sp][mt][3], ad);
                }
#pragma unroll
                for (int nt = 0; nt < 2; nt++) {
                    unsigned bd = tb + (unsigned)((1 + sp * 2) * MATB) + b_off
                                + (unsigned)((wn + nt * 16) * ROWB + kk * 2);
                    LDMATRIX_X4(bfr[sp][nt][0], bfr[sp][nt][1],
                                bfr[sp][nt][2], bfr[sp][nt][3], bd);
                }
            }
#pragma unroll
            for (int mt = 0; mt < 4; mt++) {
#pragma unroll
                for (int nt = 0; nt < 4; nt++) {
                    const int pr = nt >> 1, hf = (nt & 1) * 2;
                    unsigned bh0 = bfr[0][pr][hf], bh1 = bfr[0][pr][hf + 1];
                    MMAF16(acc[mt][nt], afr[0][mt][0], afr[0][mt][1],
                           afr[0][mt][2], afr[0][mt][3], bh0, bh1);
                    if (SPLIT == 3) {
                        unsigned bl0 = bfr[1][pr][hf], bl1 = bfr[1][pr][hf + 1];
                        MMAF16(acc[mt][nt], afr[0][mt][0], afr[0][mt][1],
                               afr[0][mt][2], afr[0][mt][3], bl0, bl1);
                        MMAF16(acc[mt][nt], afr[1][mt][0], afr[1][mt][1],
                               afr[1][mt][2], afr[1][mt][3], bh0, bh1);
                    }
                }
            }
        }
        __syncthreads();
    }

    // ---- epilogue ----
    const int r0 = lane >> 2, c0 = (lane & 3) * 2;
#pragma unroll
    for (int mt = 0; mt < 4; mt++) {
#pragma unroll
        for (int nt = 0; nt < 4; nt++) {
            int row = m0 + wm + mt * 16 + r0;
            int col = n0 + wn + nt * 8 + c0;
            float v0 = acc[mt][nt][0], v1 = acc[mt][nt][1];
            float v2 = acc[mt][nt][2], v3 = acc[mt][nt][3];
            if (OUTM == 0) {
                float* Cp = Cf + (size_t)row * N + col;
                *(float2*)Cp = make_float2(v0, v1);
                *(float2*)(Cp + (size_t)8 * N) = make_float2(v2, v3);
            } else if (OUTM == 2) {
                *(unsigned*)(Ch + (size_t)row * N + col) = pack2h(v0, v1);
                *(unsigned*)(Ch + (size_t)(row + 8) * N + col) = pack2h(v2, v3);
            } else {
                __half h0 = __float2half_rn(v0), h1 = __float2half_rn(v1);
                __half h2 = __float2half_rn(v2), h3 = __float2half_rn(v3);
                *(unsigned*)(Ch + (size_t)row * N + col) =
                    *(unsigned*)&h0 | (*(unsigned*)&h1 << 16);
                *(unsigned*)(Ch + (size_t)(row + 8) * N + col) =
                    *(unsigned*)&h2 | (*(unsigned*)&h3 << 16);
                *(unsigned*)(Cl + (size_t)row * N + col) =
                    pack2h(v0 - __half2float(h0), v1 - __half2float(h1));
                *(unsigned*)(Cl + (size_t)(row + 8) * N + col) =
                    pack2h(v2 - __half2float(h2), v3 - __half2float(h3));
            }
        }
    }
}

// ---------------------------------------------------------------------------
// HMMA flash attention: 128q x 128k tiles, 8 warps (16 q-rows each).
// QK split-fp16 (3 MMAs), PV single fp16 via fragment chaining + ldmatrix.trans.
// ---------------------------------------------------------------------------
#define FPITCH 144
#define FMAT (128 * FPITCH)                   // 18432
#define FSTAGE (3 * FMAT)                     // Kh, Kl, V
#define FQOFF (2 * FSTAGE)                    // 110592
#define FLASH_SMEM (FQOFF + 2 * FMAT)         // 147456

__device__ __forceinline__ void load_tile_f(unsigned sdst, const __half* g, int tid) {
#pragma unroll
    for (int i = 0; i < 4; i++) {
        int c = tid + i * 256;
        int row = c >> 3, ch = c & 7;
        CP_ASYNC16(sdst + (unsigned)(row * FPITCH + ch * 16),
                   g + (size_t)row * DMODEL + ch * 8);
    }
}

__global__ __launch_bounds__(256, 1)
void flash_hmma(const __half* __restrict__ Qh, const __half* __restrict__ Ql,
                const __half* __restrict__ Kh, const __half* __restrict__ Kl,
                const __half* __restrict__ Vf, const float* __restrict__ tbl,
                __half* __restrict__ Oh) {
    extern __shared__ char sm[];
    __shared__ float tcol[32];
    __shared__ float bias183[184];
    const unsigned sb = smem_u32(sm);
    const int tid = threadIdx.x, wid = tid >> 5, lane = tid & 31;
    const int q0 = blockIdx.x * 128, h = blockIdx.y, b = blockIdx.z;

    const size_t qbase = ((size_t)(b * S_LEN + q0)) * DMODEL + h * DKV;
    const size_t kbase = ((size_t)(b * S_LEN)) * DMODEL + h * DKV;

    // group 0: Q (hi+lo) + tile 0 (Kh, Kl, V)
    load_tile_f(sb + FQOFF, Qh + qbase, tid);
    load_tile_f(sb + FQOFF + FMAT, Ql + qbase, tid);
    load_tile_f(sb, Kh + kbase, tid);
    load_tile_f(sb + FMAT, Kl + kbase, tid);
    load_tile_f(sb + 2 * FMAT, Vf + kbase, tid);
    CP_COMMIT();

    if (tid < 32) tcol[tid] = tbl[tid * NHEADS + h];
    __syncthreads();
    if (tid < 183) bias183[tid] = tcol[rel_bucket(tid - 91)];

    const int u = lane & 3, g = lane >> 2;
    const int qA = q0 + wid * 16 + g;     // global q row of c0/c1
    const int qB = qA + 8;                // global q row of c2/c3

    const unsigned aoff = (unsigned)((lane & 15) * FPITCH + (lane >> 4) * 16);
    const unsigned boff = (unsigned)(((((lane >> 4) << 3) | (lane & 7)) * FPITCH)
                                     + ((lane >> 3) & 1) * 16);
    const unsigned voff = (unsigned)(((((lane >> 3) & 1) * 8 + (lane & 7)) * FPITCH)
                                     + (lane >> 4) * 16);

    unsigned aqh[4][4], aql[4][4];
    float accO[8][4];
#pragma unroll
    for (int i = 0; i < 8; i++)
#pragma unroll
        for (int j = 0; j < 4; j++) accO[i][j] = 0.0f;
    float mA = -1e30f, mB = -1e30f, lA = 0.0f, lB = 0.0f;

    for (int t = 0; t < 16; t++) {
        if (t + 1 < 16) {
            unsigned st = sb + (unsigned)(((t + 1) & 1) * FSTAGE);
            size_t kb2 = kbase + (size_t)(t + 1) * 128 * DMODEL;
            load_tile_f(st, Kh + kb2, tid);
            load_tile_f(st + FMAT, Kl + kb2, tid);
            load_tile_f(st + 2 * FMAT, Vf + kb2, tid);
            CP_COMMIT();
            CP_WAIT1();
        } else {
            CP_WAIT0();
        }
        __syncthreads();

        if (t == 0) {
            // build Q register fragments (m16 x k64, hi and lo)
#pragma unroll
            for (int c = 0; c < 4; c++) {
                unsigned qa = sb + FQOFF + (unsigned)(wid * 16 * FPITCH) + aoff
                            + (unsigned)(c * 32);
                LDMATRIX_X4(aqh[c][0], aqh[c][1], aqh[c][2], aqh[c][3], qa);
                LDMATRIX_X4(aql[c][0], aql[c][1], aql[c][2], aql[c][3], qa + FMAT);
            }
        }

        const unsigned stg = sb + (unsigned)((t & 1) * FSTAGE);

        // ---- S = Q K^T (split fp16, f32 accum) ----
        float accS[16][4];
#pragma unroll
        for (int i = 0; i < 16; i++)
#pragma unroll
            for (int j = 0; j < 4; j++) accS[i][j] = 0.0f;

#pragma unroll
        for (int c = 0; c < 4; c++) {
#pragma unroll
            for (int gg = 0; gg < 8; gg++) {
                unsigned bh0, bh1, bh2, bh3, bl0, bl1, bl2, bl3;
                unsigned ka = stg + boff + (unsigned)(gg * 16 * FPITCH + c * 32);
                LDMATRIX_X4(bh0, bh1, bh2, bh3, ka);
                LDMATRIX_X4(bl0, bl1, bl2, bl3, ka + FMAT);
                MMAF16(accS[2 * gg], aqh[c][0], aqh[c][1], aqh[c][2], aqh[c][3], bh0, bh1);
                MMAF16(accS[2 * gg + 1], aqh[c][0], aqh[c][1], aqh[c][2], aqh[c][3], bh2, bh3);
                MMAF16(accS[2 * gg], aqh[c][0], aqh[c][1], aqh[c][2], aqh[c][3], bl0, bl1);
                MMAF16(accS[2 * gg + 1], aqh[c][0], aqh[c][1], aqh[c][2], aqh[c][3], bl2, bl3);
                MMAF16(accS[2 * gg], aql[c][0], aql[c][1], aql[c][2], aql[c][3], bh0, bh1);
                MMAF16(accS[2 * gg + 1], aql[c][0], aql[c][1], aql[c][2], aql[c][3], bh2, bh3);
            }
        }

        // ---- bias + online softmax ----
        const int k0 = t * 128;
        float tmA = -1e30f, tmB = -1e30f;
#pragma unroll
        for (int s8 = 0; s8 < 16; s8++) {
            int kc = k0 + s8 * 8 + 2 * u;
            int iA0 = min(max(kc - qA, -91), 91) + 91;
            int iA1 = min(max(kc + 1 - qA, -91), 91) + 91;
            int iB0 = min(max(kc - qB, -91), 91) + 91;
            int iB1 = min(max(kc + 1 - qB, -91), 91) + 91;
            accS[s8][0] += bias183[iA0];
            accS[s8][1] += bias183[iA1];
            accS[s8][2] += bias183[iB0];
            accS[s8][3] += bias183[iB1];
            tmA = fmaxf(tmA, fmaxf(accS[s8][0], accS[s8][1]));
            tmB = fmaxf(tmB, fmaxf(accS[s8][2], accS[s8][3]));
        }
        tmA = fmaxf(tmA, __shfl_xor_sync(0xffffffffu, tmA, 1));
        tmA = fmaxf(tmA, __shfl_xor_sync(0xffffffffu, tmA, 2));
        tmB = fmaxf(tmB, __shfl_xor_sync(0xffffffffu, tmB, 1));
        tmB = fmaxf(tmB, __shfl_xor_sync(0xffffffffu, tmB, 2));

        float nmA = fmaxf(mA, tmA), scA = __expf(mA - nmA);
        float nmB = fmaxf(mB, tmB), scB = __expf(mB - nmB);
        mA = nmA; mB = nmB;

        float sA = 0.0f, sB = 0.0f;
#pragma unroll
        for (int s8 = 0; s8 < 16; s8++) {
            accS[s8][0] = __expf(accS[s8][0] - nmA);
            accS[s8][1] = __expf(accS[s8][1] - nmA);
            accS[s8][2] = __expf(accS[s8][2] - nmB);
            accS[s8][3] = __expf(accS[s8][3] - nmB);
            sA += accS[s8][0] + accS[s8][1];
            sB += accS[s8][2] + accS[s8][3];
        }
        sA += __shfl_xor_sync(0xffffffffu, sA, 1);
        sA += __shfl_xor_sync(0xffffffffu, sA, 2);
        sB += __shfl_xor_sync(0xffffffffu, sB, 1);
        sB += __shfl_xor_sync(0xffffffffu, sB, 2);
        lA = lA * scA + sA;
        lB = lB * scB + sB;

#pragma unroll
        for (int nt = 0; nt < 8; nt++) {
            accO[nt][0] *= scA; accO[nt][1] *= scA;
            accO[nt][2] *= scB; accO[nt][3] *= scB;
        }

        // ---- O += P V (fragment chaining, fp16 P & V) ----
#pragma unroll
        for (int j = 0; j < 8; j++) {
            unsigned a0 = pack2h(accS[2 * j][0], accS[2 * j][1]);
            unsigned a1 = pack2h(accS[2 * j][2], accS[2 * j][3]);
            unsigned a2 = pack2h(accS[2 * j + 1][0], accS[2 * j + 1][1]);
            unsigned a3 = pack2h(accS[2 * j + 1][2], accS[2 * j + 1][3]);
#pragma unroll
            for (int g2 = 0; g2 < 4; g2++) {
                unsigned bv0, bv1, bv2, bv3;
                unsigned va = stg + (unsigned)(2 * FMAT) + voff
                            + (unsigned)(j * 16 * FPITCH + g2 * 32);
                LDMATRIX_X4_T(bv0, bv1, bv2, bv3, va);
                MMAF16(accO[2 * g2], a0, a1, a2, a3, bv0, bv1);
                MMAF16(accO[2 * g2 + 1], a0, a1, a2, a3, bv2, bv3);
            }
        }
        __syncthreads();
    }

    // ---- epilogue: normalize, write fp16 ----
    const float iA = 1.0f / lA, iB = 1.0f / lB;
    const size_t rowA = (size_t)(b * S_LEN + qA) * DMODEL + h * DKV;
    const size_t rowB = (size_t)(b * S_LEN + qB) * DMODEL + h * DKV;
#pragma unroll
    for (int nt = 0; nt < 8; nt++) {
        int col = nt * 8 + 2 * u;
        *(unsigned*)(Oh + rowA + col) = pack2h(accO[nt][0] * iA, accO[nt][1] * iA);
        *(unsigned*)(Oh + rowB + col) = pack2h(accO[nt][2] * iB, accO[nt][3] * iB);
    }
}

// ---------------------------------------------------------------------------
extern "C" void kernel_launch(void* const* d_in, const int* in_sizes, int n_in,
                              void* d_out, int out_size) {
    const float* X   = (const float*)d_in[0];
    const float* Wq  = (const float*)d_in[1];
    const float* Wk  = (const float*)d_in[2];
    const float* Wv  = (const float*)d_in[3];
    const float* Wo  = (const float*)d_in[4];
    const float* tbl = (const float*)d_in[5];
    float* out = (float*)d_out;

    __half *xh, *xl, *wqh, *wql, *wkh, *wkl, *wvh, *wvl, *woh, *wol;
    __half *qh, *ql, *kh, *kl, *vh, *oh;
    cudaGetSymbolAddress((void**)&xh, g_xh);
    cudaGetSymbolAddress((void**)&xl, g_xl);
    cudaGetSymbolAddress((void**)&wqh, g_wqh);
    cudaGetSymbolAddress((void**)&wql, g_wql);
    cudaGetSymbolAddress((void**)&wkh, g_wkh);
    cudaGetSymbolAddress((void**)&wkl, g_wkl);
    cudaGetSymbolAddress((void**)&wvh, g_wvh);
    cudaGetSymbolAddress((void**)&wvl, g_wvl);
    cudaGetSymbolAddress((void**)&woh, g_woh);
    cudaGetSymbolAddress((void**)&wol, g_wol);
    cudaGetSymbolAddress((void**)&qh, g_qh);
    cudaGetSymbolAddress((void**)&ql, g_ql);
    cudaGetSymbolAddress((void**)&kh, g_kh);
    cudaGetSymbolAddress((void**)&kl, g_kl);
    cudaGetSymbolAddress((void**)&vh, g_vh);
    cudaGetSymbolAddress((void**)&oh, g_oh);

    // pos_bias (independent)
    {
        dim3 bg(S_LEN, NHEADS);
        bias_kernel<<<bg, 256>>>(tbl, out + OUT_ELEMS);
    }

    // conversions
    {
        int n4 = OUT_ELEMS / 4;
        split_kernel<<<(n4 + 255) / 256, 256>>>(X, xh, xl, n4);
        dim3 tb(32, 8), tg(32, 32);
        transpose_split<<<tg, tb>>>(Wq, wqh, wql);
        transpose_split<<<tg, tb>>>(Wk, wkh, wkl);
        transpose_split<<<tg, tb>>>(Wv, wvh, wvl);
        transpose_split<<<tg, tb>>>(Wo, woh, wol);
    }

    dim3 gg(DMODEL / 128, M_ROWS / 128);

    // Q, K projections: split (logit-critical), epilogue emits fp16 hi/lo
    cudaFuncSetAttribute(gemm_h<3, 1>, cudaFuncAttributeMaxDynamicSharedMemorySize,
                         GSTAGES * 4 * MATB);
    gemm_h<3, 1><<<gg, 256, GSTAGES * 4 * MATB>>>(xh, xl, wqh, wql,
                                                  nullptr, qh, ql,
                                                  M_ROWS, DMODEL, DMODEL);
    gemm_h<3, 1><<<gg, 256, GSTAGES * 4 * MATB>>>(xh, xl, wkh, wkl,
                                                  nullptr, kh, kl,
                                                  M_ROWS, DMODEL, DMODEL);

    // V projection: single-pass fp16 (linear path)
    cudaFuncSetAttribute(gemm_h<1, 2>, cudaFuncAttributeMaxDynamicSharedMemorySize,
                         GSTAGES * 2 * MATB);
    gemm_h<1, 2><<<gg, 256, GSTAGES * 2 * MATB>>>(xh, nullptr, wvh, nullptr,
                                                  nullptr, vh, nullptr,
                                                  M_ROWS, DMODEL, DMODEL);

    // flash attention (HMMA)
    cudaFuncSetAttribute(flash_hmma, cudaFuncAttributeMaxDynamicSharedMemorySize,
                         FLASH_SMEM);
    dim3 fg(S_LEN / 128, NHEADS, BATCH);
    flash_hmma<<<fg, 256, FLASH_SMEM>>>(qh, ql, kh, kl, vh, tbl, oh);

    // output projection: single-pass fp16, f32 out
    cudaFuncSetAttribute(gemm_h<1, 0>, cudaFuncAttributeMaxDynamicSharedMemorySize,
                         GSTAGES * 2 * MATB);
    gemm_h<1, 0><<<gg, 256, GSTAGES * 2 * MATB>>>(oh, nullptr, woh, nullptr,
                                                  out, nullptr, nullptr,
                                                  M_ROWS, DMODEL, DMODEL);
}

// round 5
// speedup vs baseline: 5.2351x; 1.1393x over previous
#include <cuda_runtime.h>
#include <cuda_fp16.h>
#include <math.h>

// Problem constants (fixed shapes)
#define S_LEN   2048
#define BATCH   4
#define NHEADS  16
#define DKV     64
#define DMODEL  1024
#define M_ROWS  (BATCH * S_LEN)                 // 8192
#define OUT_ELEMS  (M_ROWS * DMODEL)            // 8388608
#define BIAS_ELEMS (NHEADS * S_LEN * S_LEN)     // 67108864

// ---------------------------------------------------------------------------
// Device scratch (fp16 everywhere)
// ---------------------------------------------------------------------------
__device__ __half g_xh[M_ROWS * DMODEL];
__device__ __half g_xl[M_ROWS * DMODEL];
__device__ __half g_wqh[DMODEL * DMODEL];
__device__ __half g_wql[DMODEL * DMODEL];
__device__ __half g_wkh[DMODEL * DMODEL];
__device__ __half g_wkl[DMODEL * DMODEL];
__device__ __half g_wvh[DMODEL * DMODEL];
__device__ __half g_wvl[DMODEL * DMODEL];
__device__ __half g_woh[DMODEL * DMODEL];
__device__ __half g_wol[DMODEL * DMODEL];
__device__ __half g_qh[M_ROWS * DMODEL];
__device__ __half g_ql[M_ROWS * DMODEL];
__device__ __half g_kh[M_ROWS * DMODEL];
__device__ __half g_kl[M_ROWS * DMODEL];
__device__ __half g_vh[M_ROWS * DMODEL];
__device__ __half g_oh[M_ROWS * DMODEL];

// ---------------------------------------------------------------------------
// PTX helpers (sm_80-level only)
// ---------------------------------------------------------------------------
__device__ __forceinline__ unsigned smem_u32(const void* p) {
    unsigned a;
    asm("{ .reg .u64 t; cvta.to.shared.u64 t, %1; cvt.u32.u64 %0, t; }"
        : "=r"(a) : "l"(p));
    return a;
}

#define LDMATRIX_X4(r0, r1, r2, r3, addr)                                      \
    asm volatile("ldmatrix.sync.aligned.m8n8.x4.shared.b16 {%0,%1,%2,%3}, [%4];" \
                 : "=r"(r0), "=r"(r1), "=r"(r2), "=r"(r3) : "r"(addr))

#define LDMATRIX_X4_T(r0, r1, r2, r3, addr)                                    \
    asm volatile("ldmatrix.sync.aligned.m8n8.x4.trans.shared.b16 {%0,%1,%2,%3}, [%4];" \
                 : "=r"(r0), "=r"(r1), "=r"(r2), "=r"(r3) : "r"(addr))

#define MMAF16(d, a0, a1, a2, a3, b0, b1)                                      \
    asm volatile("mma.sync.aligned.m16n8k16.row.col.f32.f16.f16.f32 "          \
                 "{%0,%1,%2,%3},{%4,%5,%6,%7},{%8,%9},{%0,%1,%2,%3};"          \
                 : "+f"((d)[0]), "+f"((d)[1]), "+f"((d)[2]), "+f"((d)[3])      \
                 : "r"(a0), "r"(a1), "r"(a2), "r"(a3), "r"(b0), "r"(b1))

#define CP_ASYNC16(dst, src)                                                   \
    asm volatile("cp.async.cg.shared.global [%0], [%1], 16;"                   \
                 :: "r"(dst), "l"(src) : "memory")
#define CP_COMMIT() asm volatile("cp.async.commit_group;" ::: "memory")
#define CP_WAIT1()  asm volatile("cp.async.wait_group 1;" ::: "memory")
#define CP_WAIT0()  asm volatile("cp.async.wait_group 0;" ::: "memory")

__device__ __forceinline__ unsigned pack2h(float a, float b) {
    __half2 h = __floats2half2_rn(a, b);
    return *reinterpret_cast<unsigned*>(&h);
}

// ---------------------------------------------------------------------------
// Relative-position bucket (exact integer reformulation of the reference)
// ---------------------------------------------------------------------------
__device__ __forceinline__ int rel_bucket(int rel) {
    int ret = (rel > 0) ? 16 : 0;
    int rp  = (rel < 0) ? -rel : rel;
    int off;
    if (rp < 8) {
        off = rp;
    } else {
        off = 8 + (rp >= 12) + (rp >= 16) + (rp >= 23) + (rp >= 32)
                + (rp >= 46) + (rp >= 64) + (rp >= 91);
    }
    return ret + off;
}

// ---------------------------------------------------------------------------
// pos_bias writer (float4 stores)
// ---------------------------------------------------------------------------
__global__ __launch_bounds__(256) void bias_kernel(const float* __restrict__ tbl,
                                                   float* __restrict__ outb) {
    __shared__ float tcol[32];
    const int q = blockIdx.x;
    const int h = blockIdx.y;
    if (threadIdx.x < 32) tcol[threadIdx.x] = tbl[threadIdx.x * NHEADS + h];
    __syncthreads();
    float4* row = (float4*)(outb + ((size_t)h * S_LEN + q) * S_LEN);
#pragma unroll
    for (int it = 0; it < 2; it++) {
        int k4 = threadIdx.x + it * 256;
        int k = k4 * 4;
        float4 v = make_float4(tcol[rel_bucket(k - q)],
                               tcol[rel_bucket(k + 1 - q)],
                               tcol[rel_bucket(k + 2 - q)],
                               tcol[rel_bucket(k + 3 - q)]);
        row[k4] = v;
    }
}

// ---------------------------------------------------------------------------
// f32 -> fp16 hi/lo split (elementwise, float4)
// ---------------------------------------------------------------------------
__global__ __launch_bounds__(256) void split_kernel(const float* __restrict__ in,
                                                    __half* __restrict__ hi,
                                                    __half* __restrict__ lo,
                                                    int n4) {
    int idx = blockIdx.x * 256 + threadIdx.x;
    if (idx >= n4) return;
    float4 v = ((const float4*)in)[idx];
    __half h0 = __float2half_rn(v.x), h1 = __float2half_rn(v.y);
    __half h2 = __float2half_rn(v.z), h3 = __float2half_rn(v.w);
    unsigned* H = (unsigned*)hi;
    unsigned* L = (unsigned*)lo;
    H[idx * 2]     = pack2h(v.x, v.y);
    H[idx * 2 + 1] = pack2h(v.z, v.w);
    L[idx * 2]     = pack2h(v.x - __half2float(h0), v.y - __half2float(h1));
    L[idx * 2 + 1] = pack2h(v.z - __half2float(h2), v.w - __half2float(h3));
}

// ---------------------------------------------------------------------------
// Batched 1024x1024 transpose + fp16 hi/lo split (2 weights per launch)
// ---------------------------------------------------------------------------
__global__ __launch_bounds__(256) void transpose_split2(
        const float* __restrict__ W0, __half* __restrict__ Th0, __half* __restrict__ Tl0,
        const float* __restrict__ W1, __half* __restrict__ Th1, __half* __restrict__ Tl1) {
    __shared__ float t[32][33];
    const float* W = blockIdx.z ? W1 : W0;
    __half* Th = blockIdx.z ? Th1 : Th0;
    __half* Tl = blockIdx.z ? Tl1 : Tl0;
    const int tx = threadIdx.x, ty = threadIdx.y;
    const int nb = blockIdx.x * 32, kb = blockIdx.y * 32;
#pragma unroll
    for (int r = ty; r < 32; r += 8)
        t[r][tx] = W[(size_t)(kb + r) * DMODEL + nb + tx];
    __syncthreads();
#pragma unroll
    for (int r = ty; r < 32; r += 8) {
        float v = t[tx][r];  // = W[kb+tx][nb+r]
        __half h = __float2half_rn(v);
        Th[(size_t)(nb + r) * DMODEL + kb + tx] = h;
        Tl[(size_t)(nb + r) * DMODEL + kb + tx] =
            __float2half_rn(v - __half2float(h));
    }
}

// ---------------------------------------------------------------------------
// HMMA fp16 GEMM, templated:
//   SPLIT==3: C = AhBh + AhBl + AlBh   SPLIT==1: C = AhBh
//   OUTM: 0 -> float C; 1 -> fp16 hi/lo pair; 2 -> fp16 single
// 128x128 CTA tile, BK=32, 4 warps @ 64x64, 2-stage cp.async, 2 CTAs/SM.
// ---------------------------------------------------------------------------
#define ROWB 80                               // 32 fp16 (64B) + 16B pad
#define MATB (128 * ROWB)                     // 10240 B

template<int SPLIT, int OUTM>
__global__ __launch_bounds__(128)
void gemm_h(const __half* __restrict__ Ah, const __half* __restrict__ Al,
            const __half* __restrict__ Bh, const __half* __restrict__ Bl,
            float* __restrict__ Cf, __half* __restrict__ Ch,
            __half* __restrict__ Cl, int M, int N, int K) {
    constexpr int NMATS = (SPLIT == 3) ? 4 : 2;
    constexpr int STAGEB = NMATS * MATB;
    extern __shared__ char smx[];
    const unsigned sb = smem_u32(smx);
    const int tid  = threadIdx.x;
    const int wid  = tid >> 5;
    const int lane = tid & 31;
    const int m0 = blockIdx.y * 128, n0 = blockIdx.x * 128;
    const int wm = (wid & 1) * 64;
    const int wn = (wid >> 1) * 64;

    // mat order: 0=Ah, 1=Bh, 2=Al, 3=Bl
    const __half* srcs[4];
    srcs[0] = Ah + (size_t)m0 * K;
    srcs[1] = Bh + (size_t)n0 * K;
    srcs[2] = (SPLIT == 3) ? (Al + (size_t)m0 * K) : srcs[0];
    srcs[3] = (SPLIT == 3) ? (Bl + (size_t)n0 * K) : srcs[1];

    const int ldrow = tid >> 2;               // 0..31
    const int ldch  = tid & 3;                // 16B chunk (4 per 64B row)

    const unsigned a_off = (unsigned)((lane & 15) * ROWB + (lane >> 4) * 16);
    const unsigned b_off = (unsigned)((((lane >> 4) << 3) + (lane & 7)) * ROWB
                                      + ((lane >> 3) & 1) * 16);

    float acc[4][8][4];
#pragma unroll
    for (int i = 0; i < 4; i++)
#pragma unroll
        for (int j = 0; j < 8; j++)
#pragma unroll
            for (int r = 0; r < 4; r++) acc[i][j][r] = 0.0f;

    const int NIT = K / 32;

    auto load_stage = [&](int s, int kit) {
        const int k0 = kit * 32;
        unsigned dbase = sb + (unsigned)(s * STAGEB);
#pragma unroll
        for (int mtx = 0; mtx < NMATS; mtx++) {
#pragma unroll
            for (int i = 0; i < 4; i++) {
                int row = ldrow + i * 32;
                unsigned dst = dbase + (unsigned)(mtx * MATB + row * ROWB + ldch * 16);
                const char* src = (const char*)(srcs[mtx] + k0 + (size_t)row * K)
                                + ldch * 16;
                CP_ASYNC16(dst, src);
            }
        }
    };

    load_stage(0, 0);
    CP_COMMIT();

    for (int kit = 0; kit < NIT; kit++) {
        if (kit + 1 < NIT) {
            load_stage((kit + 1) & 1, kit + 1);
            CP_COMMIT();
            CP_WAIT1();
        } else {
            CP_WAIT0();
        }
        __syncthreads();

        const unsigned tb = sb + (unsigned)((kit & 1) * STAGEB);
#pragma unroll
        for (int kk = 0; kk < 32; kk += 16) {
            constexpr int NSP = (SPLIT == 3) ? 2 : 1;
            unsigned afr[NSP][4][4];
            unsigned bfr[NSP][4][4];
#pragma unroll
            for (int sp = 0; sp < NSP; sp++) {
#pragma unroll
                for (int mt = 0; mt < 4; mt++) {
                    unsigned ad = tb + (unsigned)(sp * 2 * MATB) + a_off
                                + (unsigned)((wm + mt * 16) * ROWB + kk * 2);
                    LDMATRIX_X4(afr[sp][mt][0], afr[sp][mt][1],
                                afr[sp][mt][2], afr[sp][mt][3], ad);
                }
#pragma unroll
                for (int nt = 0; nt < 4; nt++) {
                    unsigned bd = tb + (unsigned)((1 + sp * 2) * MATB) + b_off
                                + (unsigned)((wn + nt * 16) * ROWB + kk * 2);
                    LDMATRIX_X4(bfr[sp][nt][0], bfr[sp][nt][1],
                                bfr[sp][nt][2], bfr[sp][nt][3], bd);
                }
            }
#pragma unroll
            for (int mt = 0; mt < 4; mt++) {
#pragma unroll
                for (int n8 = 0; n8 < 8; n8++) {
                    const int pr = n8 >> 1, hf = (n8 & 1) * 2;
                    unsigned bh0 = bfr[0][pr][hf], bh1 = bfr[0][pr][hf + 1];
                    MMAF16(acc[mt][n8], afr[0][mt][0], afr[0][mt][1],
                           afr[0][mt][2], afr[0][mt][3], bh0, bh1);
                    if (SPLIT == 3) {
                        unsigned bl0 = bfr[1][pr][hf], bl1 = bfr[1][pr][hf + 1];
                        MMAF16(acc[mt][n8], afr[0][mt][0], afr[0][mt][1],
                               afr[0][mt][2], afr[0][mt][3], bl0, bl1);
                        MMAF16(acc[mt][n8], afr[1][mt][0], afr[1][mt][1],
                               afr[1][mt][2], afr[1][mt][3], bh0, bh1);
                    }
                }
            }
        }
        __syncthreads();
    }

    // ---- epilogue ----
    const int r0 = lane >> 2, c0 = (lane & 3) * 2;
#pragma unroll
    for (int mt = 0; mt < 4; mt++) {
#pragma unroll
        for (int n8 = 0; n8 < 8; n8++) {
            int row = m0 + wm + mt * 16 + r0;
            int col = n0 + wn + n8 * 8 + c0;
            float v0 = acc[mt][n8][0], v1 = acc[mt][n8][1];
            float v2 = acc[mt][n8][2], v3 = acc[mt][n8][3];
            if (OUTM == 0) {
                float* Cp = Cf + (size_t)row * N + col;
                *(float2*)Cp = make_float2(v0, v1);
                *(float2*)(Cp + (size_t)8 * N) = make_float2(v2, v3);
            } else if (OUTM == 2) {
                *(unsigned*)(Ch + (size_t)row * N + col) = pack2h(v0, v1);
                *(unsigned*)(Ch + (size_t)(row + 8) * N + col) = pack2h(v2, v3);
            } else {
                __half h0 = __float2half_rn(v0), h1 = __float2half_rn(v1);
                __half h2 = __float2half_rn(v2), h3 = __float2half_rn(v3);
                *(unsigned*)(Ch + (size_t)row * N + col) =
                    *(unsigned*)&h0 | (*(unsigned*)&h1 << 16);
                *(unsigned*)(Ch + (size_t)(row + 8) * N + col) =
                    *(unsigned*)&h2 | (*(unsigned*)&h3 << 16);
                *(unsigned*)(Cl + (size_t)row * N + col) =
                    pack2h(v0 - __half2float(h0), v1 - __half2float(h1));
                *(unsigned*)(Cl + (size_t)(row + 8) * N + col) =
                    pack2h(v2 - __half2float(h2), v3 - __half2float(h3));
            }
        }
    }
}

// ---------------------------------------------------------------------------
// HMMA flash attention: 128q x 128k tiles, 8 warps (16 q-rows each).
// QK split-fp16 (3 MMAs), PV single fp16 via fragment chaining + ldmatrix.trans.
// ---------------------------------------------------------------------------
#define FPITCH 144
#define FMAT (128 * FPITCH)                   // 18432
#define FSTAGE (3 * FMAT)                     // Kh, Kl, V
#define FQOFF (2 * FSTAGE)                    // 110592
#define FLASH_SMEM (FQOFF + 2 * FMAT)         // 147456

__device__ __forceinline__ void load_tile_f(unsigned sdst, const __half* g, int tid) {
#pragma unroll
    for (int i = 0; i < 4; i++) {
        int c = tid + i * 256;
        int row = c >> 3, ch = c & 7;
        CP_ASYNC16(sdst + (unsigned)(row * FPITCH + ch * 16),
                   g + (size_t)row * DMODEL + ch * 8);
    }
}

__global__ __launch_bounds__(256, 1)
void flash_hmma(const __half* __restrict__ Qh, const __half* __restrict__ Ql,
                const __half* __restrict__ Kh, const __half* __restrict__ Kl,
                const __half* __restrict__ Vf, const float* __restrict__ tbl,
                __half* __restrict__ Oh) {
    extern __shared__ char sm[];
    __shared__ float tcol[32];
    __shared__ float bias183[184];
    const unsigned sb = smem_u32(sm);
    const int tid = threadIdx.x, wid = tid >> 5, lane = tid & 31;
    const int q0 = blockIdx.x * 128, h = blockIdx.y, b = blockIdx.z;

    const size_t qbase = ((size_t)(b * S_LEN + q0)) * DMODEL + h * DKV;
    const size_t kbase = ((size_t)(b * S_LEN)) * DMODEL + h * DKV;

    // group 0: Q (hi+lo) + tile 0 (Kh, Kl, V)
    load_tile_f(sb + FQOFF, Qh + qbase, tid);
    load_tile_f(sb + FQOFF + FMAT, Ql + qbase, tid);
    load_tile_f(sb, Kh + kbase, tid);
    load_tile_f(sb + FMAT, Kl + kbase, tid);
    load_tile_f(sb + 2 * FMAT, Vf + kbase, tid);
    CP_COMMIT();

    if (tid < 32) tcol[tid] = tbl[tid * NHEADS + h];
    __syncthreads();
    if (tid < 183) bias183[tid] = tcol[rel_bucket(tid - 91)];

    const int u = lane & 3, g = lane >> 2;
    const int qA = q0 + wid * 16 + g;     // global q row of c0/c1
    const int qB = qA + 8;                // global q row of c2/c3

    const unsigned aoff = (unsigned)((lane & 15) * FPITCH + (lane >> 4) * 16);
    const unsigned boff = (unsigned)(((((lane >> 4) << 3) | (lane & 7)) * FPITCH)
                                     + ((lane >> 3) & 1) * 16);
    const unsigned voff = (unsigned)(((((lane >> 3) & 1) * 8 + (lane & 7)) * FPITCH)
                                     + (lane >> 4) * 16);

    unsigned aqh[4][4], aql[4][4];
    float accO[8][4];
#pragma unroll
    for (int i = 0; i < 8; i++)
#pragma unroll
        for (int j = 0; j < 4; j++) accO[i][j] = 0.0f;
    float mA = -1e30f, mB = -1e30f, lA = 0.0f, lB = 0.0f;

    for (int t = 0; t < 16; t++) {
        if (t + 1 < 16) {
            unsigned st = sb + (unsigned)(((t + 1) & 1) * FSTAGE);
            size_t kb2 = kbase + (size_t)(t + 1) * 128 * DMODEL;
            load_tile_f(st, Kh + kb2, tid);
            load_tile_f(st + FMAT, Kl + kb2, tid);
            load_tile_f(st + 2 * FMAT, Vf + kb2, tid);
            CP_COMMIT();
            CP_WAIT1();
        } else {
            CP_WAIT0();
        }
        __syncthreads();

        if (t == 0) {
            // build Q register fragments (m16 x k64, hi and lo)
#pragma unroll
            for (int c = 0; c < 4; c++) {
                unsigned qa = sb + FQOFF + (unsigned)(wid * 16 * FPITCH) + aoff
                            + (unsigned)(c * 32);
                LDMATRIX_X4(aqh[c][0], aqh[c][1], aqh[c][2], aqh[c][3], qa);
                LDMATRIX_X4(aql[c][0], aql[c][1], aql[c][2], aql[c][3], qa + FMAT);
            }
        }

        const unsigned stg = sb + (unsigned)((t & 1) * FSTAGE);

        // ---- S = Q K^T (split fp16, f32 accum) ----
        float accS[16][4];
#pragma unroll
        for (int i = 0; i < 16; i++)
#pragma unroll
            for (int j = 0; j < 4; j++) accS[i][j] = 0.0f;

#pragma unroll
        for (int c = 0; c < 4; c++) {
#pragma unroll
            for (int gg = 0; gg < 8; gg++) {
                unsigned bh0, bh1, bh2, bh3, bl0, bl1, bl2, bl3;
                unsigned ka = stg + boff + (unsigned)(gg * 16 * FPITCH + c * 32);
                LDMATRIX_X4(bh0, bh1, bh2, bh3, ka);
                LDMATRIX_X4(bl0, bl1, bl2, bl3, ka + FMAT);
                MMAF16(accS[2 * gg], aqh[c][0], aqh[c][1], aqh[c][2], aqh[c][3], bh0, bh1);
                MMAF16(accS[2 * gg + 1], aqh[c][0], aqh[c][1], aqh[c][2], aqh[c][3], bh2, bh3);
                MMAF16(accS[2 * gg], aqh[c][0], aqh[c][1], aqh[c][2], aqh[c][3], bl0, bl1);
                MMAF16(accS[2 * gg + 1], aqh[c][0], aqh[c][1], aqh[c][2], aqh[c][3], bl2, bl3);
                MMAF16(accS[2 * gg], aql[c][0], aql[c][1], aql[c][2], aql[c][3], bh0, bh1);
                MMAF16(accS[2 * gg + 1], aql[c][0], aql[c][1], aql[c][2], aql[c][3], bh2, bh3);
            }
        }

        // ---- bias + online softmax ----
        const int k0 = t * 128;
        float tmA = -1e30f, tmB = -1e30f;
#pragma unroll
        for (int s8 = 0; s8 < 16; s8++) {
            int kc = k0 + s8 * 8 + 2 * u;
            int iA0 = min(max(kc - qA, -91), 91) + 91;
            int iA1 = min(max(kc + 1 - qA, -91), 91) + 91;
            int iB0 = min(max(kc - qB, -91), 91) + 91;
            int iB1 = min(max(kc + 1 - qB, -91), 91) + 91;
            accS[s8][0] += bias183[iA0];
            accS[s8][1] += bias183[iA1];
            accS[s8][2] += bias183[iB0];
            accS[s8][3] += bias183[iB1];
            tmA = fmaxf(tmA, fmaxf(accS[s8][0], accS[s8][1]));
            tmB = fmaxf(tmB, fmaxf(accS[s8][2], accS[s8][3]));
        }
        tmA = fmaxf(tmA, __shfl_xor_sync(0xffffffffu, tmA, 1));
        tmA = fmaxf(tmA, __shfl_xor_sync(0xffffffffu, tmA, 2));
        tmB = fmaxf(tmB, __shfl_xor_sync(0xffffffffu, tmB, 1));
        tmB = fmaxf(tmB, __shfl_xor_sync(0xffffffffu, tmB, 2));

        float nmA = fmaxf(mA, tmA), scA = __expf(mA - nmA);
        float nmB = fmaxf(mB, tmB), scB = __expf(mB - nmB);
        mA = nmA; mB = nmB;

        float sA = 0.0f, sB = 0.0f;
#pragma unroll
        for (int s8 = 0; s8 < 16; s8++) {
            accS[s8][0] = __expf(accS[s8][0] - nmA);
            accS[s8][1] = __expf(accS[s8][1] - nmA);
            accS[s8][2] = __expf(accS[s8][2] - nmB);
            accS[s8][3] = __expf(accS[s8][3] - nmB);
            sA += accS[s8][0] + accS[s8][1];
            sB += accS[s8][2] + accS[s8][3];
        }
        sA += __shfl_xor_sync(0xffffffffu, sA, 1);
        sA += __shfl_xor_sync(0xffffffffu, sA, 2);
        sB += __shfl_xor_sync(0xffffffffu, sB, 1);
        sB += __shfl_xor_sync(0xffffffffu, sB, 2);
        lA = lA * scA + sA;
        lB = lB * scB + sB;

#pragma unroll
        for (int nt = 0; nt < 8; nt++) {
            accO[nt][0] *= scA; accO[nt][1] *= scA;
            accO[nt][2] *= scB; accO[nt][3] *= scB;
        }

        // ---- O += P V (fragment chaining, fp16 P & V) ----
#pragma unroll
        for (int j = 0; j < 8; j++) {
            unsigned a0 = pack2h(accS[2 * j][0], accS[2 * j][1]);
            unsigned a1 = pack2h(accS[2 * j][2], accS[2 * j][3]);
            unsigned a2 = pack2h(accS[2 * j + 1][0], accS[2 * j + 1][1]);
            unsigned a3 = pack2h(accS[2 * j + 1][2], accS[2 * j + 1][3]);
#pragma unroll
            for (int g2 = 0; g2 < 4; g2++) {
                unsigned bv0, bv1, bv2, bv3;
                unsigned va = stg + (unsigned)(2 * FMAT) + voff
                            + (unsigned)(j * 16 * FPITCH + g2 * 32);
                LDMATRIX_X4_T(bv0, bv1, bv2, bv3, va);
                MMAF16(accO[2 * g2], a0, a1, a2, a3, bv0, bv1);
                MMAF16(accO[2 * g2 + 1], a0, a1, a2, a3, bv2, bv3);
            }
        }
        __syncthreads();
    }

    // ---- epilogue: normalize, write fp16 ----
    const float iA = 1.0f / lA, iB = 1.0f / lB;
    const size_t rowA = (size_t)(b * S_LEN + qA) * DMODEL + h * DKV;
    const size_t rowB = (size_t)(b * S_LEN + qB) * DMODEL + h * DKV;
#pragma unroll
    for (int nt = 0; nt < 8; nt++) {
        int col = nt * 8 + 2 * u;
        *(unsigned*)(Oh + rowA + col) = pack2h(accO[nt][0] * iA, accO[nt][1] * iA);
        *(unsigned*)(Oh + rowB + col) = pack2h(accO[nt][2] * iB, accO[nt][3] * iB);
    }
}

// ---------------------------------------------------------------------------
extern "C" void kernel_launch(void* const* d_in, const int* in_sizes, int n_in,
                              void* d_out, int out_size) {
    const float* X   = (const float*)d_in[0];
    const float* Wq  = (const float*)d_in[1];
    const float* Wk  = (const float*)d_in[2];
    const float* Wv  = (const float*)d_in[3];
    const float* Wo  = (const float*)d_in[4];
    const float* tbl = (const float*)d_in[5];
    float* out = (float*)d_out;

    __half *xh, *xl, *wqh, *wql, *wkh, *wkl, *wvh, *wvl, *woh, *wol;
    __half *qh, *ql, *kh, *kl, *vh, *oh;
    cudaGetSymbolAddress((void**)&xh, g_xh);
    cudaGetSymbolAddress((void**)&xl, g_xl);
    cudaGetSymbolAddress((void**)&wqh, g_wqh);
    cudaGetSymbolAddress((void**)&wql, g_wql);
    cudaGetSymbolAddress((void**)&wkh, g_wkh);
    cudaGetSymbolAddress((void**)&wkl, g_wkl);
    cudaGetSymbolAddress((void**)&wvh, g_wvh);
    cudaGetSymbolAddress((void**)&wvl, g_wvl);
    cudaGetSymbolAddress((void**)&woh, g_woh);
    cudaGetSymbolAddress((void**)&wol, g_wol);
    cudaGetSymbolAddress((void**)&qh, g_qh);
    cudaGetSymbolAddress((void**)&ql, g_ql);
    cudaGetSymbolAddress((void**)&kh, g_kh);
    cudaGetSymbolAddress((void**)&kl, g_kl);
    cudaGetSymbolAddress((void**)&vh, g_vh);
    cudaGetSymbolAddress((void**)&oh, g_oh);

    // Launch order chosen so ncu (-s 5 -c 1) captures launch #5 = gemm_h<3,1>
    // (K projection, the heaviest kernel class).

    // 0: pos_bias (independent)
    {
        dim3 bg(S_LEN, NHEADS);
        bias_kernel<<<bg, 256>>>(tbl, out + OUT_ELEMS);
    }

    // 1: activation split; 2-3: weight transposes (batched x2)
    {
        int n4 = OUT_ELEMS / 4;
        split_kernel<<<(n4 + 255) / 256, 256>>>(X, xh, xl, n4);
        dim3 tb(32, 8), tg(32, 32, 2);
        transpose_split2<<<tg, tb>>>(Wq, wqh, wql, Wk, wkh, wkl);
        transpose_split2<<<tg, tb>>>(Wv, wvh, wvl, Wo, woh, wol);
    }

    dim3 gg(DMODEL / 128, M_ROWS / 128);

    // 4-5: Q, K projections (split, fp16 hi/lo outputs)
    cudaFuncSetAttribute(gemm_h<3, 1>, cudaFuncAttributeMaxDynamicSharedMemorySize,
                         2 * 4 * MATB);
    gemm_h<3, 1><<<gg, 128, 2 * 4 * MATB>>>(xh, xl, wqh, wql,
                                            nullptr, qh, ql,
                                            M_ROWS, DMODEL, DMODEL);
    gemm_h<3, 1><<<gg, 128, 2 * 4 * MATB>>>(xh, xl, wkh, wkl,
                                            nullptr, kh, kl,
                                            M_ROWS, DMODEL, DMODEL);

    // 6: V projection (single-pass fp16)
    cudaFuncSetAttribute(gemm_h<1, 2>, cudaFuncAttributeMaxDynamicSharedMemorySize,
                         2 * 2 * MATB);
    gemm_h<1, 2><<<gg, 128, 2 * 2 * MATB>>>(xh, nullptr, wvh, nullptr,
                                            nullptr, vh, nullptr,
                                            M_ROWS, DMODEL, DMODEL);

    // 7: flash attention (HMMA)
    cudaFuncSetAttribute(flash_hmma, cudaFuncAttributeMaxDynamicSharedMemorySize,
                         FLASH_SMEM);
    dim3 fg(S_LEN / 128, NHEADS, BATCH);
    flash_hmma<<<fg, 256, FLASH_SMEM>>>(qh, ql, kh, kl, vh, tbl, oh);

    // 8: output projection (single-pass fp16, f32 out)
    cudaFuncSetAttribute(gemm_h<1, 0>, cudaFuncAttributeMaxDynamicSharedMemorySize,
                         2 * 2 * MATB);
    gemm_h<1, 0><<<gg, 128, 2 * 2 * MATB>>>(oh, nullptr, woh, nullptr,
                                            out, nullptr, nullptr,
                                            M_ROWS, DMODEL, DMODEL);
}

// round 6
// speedup vs baseline: 5.2787x; 1.0083x over previous
#include <cuda_runtime.h>
#include <cuda_fp16.h>
#include <math.h>

// Problem constants (fixed shapes)
#define S_LEN   2048
#define BATCH   4
#define NHEADS  16
#define DKV     64
#define DMODEL  1024
#define M_ROWS  (BATCH * S_LEN)                 // 8192
#define OUT_ELEMS  (M_ROWS * DMODEL)            // 8388608
#define BIAS_ELEMS (NHEADS * S_LEN * S_LEN)     // 67108864

// ---------------------------------------------------------------------------
// Device scratch (fp16 everywhere)
// ---------------------------------------------------------------------------
__device__ __half g_xh[M_ROWS * DMODEL];
__device__ __half g_xl[M_ROWS * DMODEL];
__device__ __half g_wqh[DMODEL * DMODEL];
__device__ __half g_wql[DMODEL * DMODEL];
__device__ __half g_wkh[DMODEL * DMODEL];
__device__ __half g_wkl[DMODEL * DMODEL];
__device__ __half g_wvh[DMODEL * DMODEL];
__device__ __half g_wvl[DMODEL * DMODEL];
__device__ __half g_woh[DMODEL * DMODEL];
__device__ __half g_wol[DMODEL * DMODEL];
__device__ __half g_qh[M_ROWS * DMODEL];
__device__ __half g_ql[M_ROWS * DMODEL];
__device__ __half g_kh[M_ROWS * DMODEL];
__device__ __half g_kl[M_ROWS * DMODEL];
__device__ __half g_vh[M_ROWS * DMODEL];
__device__ __half g_oh[M_ROWS * DMODEL];

// ---------------------------------------------------------------------------
// PTX helpers (sm_80-level only)
// ---------------------------------------------------------------------------
__device__ __forceinline__ unsigned smem_u32(const void* p) {
    unsigned a;
    asm("{ .reg .u64 t; cvta.to.shared.u64 t, %1; cvt.u32.u64 %0, t; }"
        : "=r"(a) : "l"(p));
    return a;
}

#define LDMATRIX_X4(r0, r1, r2, r3, addr)                                      \
    asm volatile("ldmatrix.sync.aligned.m8n8.x4.shared.b16 {%0,%1,%2,%3}, [%4];" \
                 : "=r"(r0), "=r"(r1), "=r"(r2), "=r"(r3) : "r"(addr))

#define LDMATRIX_X4_T(r0, r1, r2, r3, addr)                                    \
    asm volatile("ldmatrix.sync.aligned.m8n8.x4.trans.shared.b16 {%0,%1,%2,%3}, [%4];" \
                 : "=r"(r0), "=r"(r1), "=r"(r2), "=r"(r3) : "r"(addr))

#define MMAF16(d, a0, a1, a2, a3, b0, b1)                                      \
    asm volatile("mma.sync.aligned.m16n8k16.row.col.f32.f16.f16.f32 "          \
                 "{%0,%1,%2,%3},{%4,%5,%6,%7},{%8,%9},{%0,%1,%2,%3};"          \
                 : "+f"((d)[0]), "+f"((d)[1]), "+f"((d)[2]), "+f"((d)[3])      \
                 : "r"(a0), "r"(a1), "r"(a2), "r"(a3), "r"(b0), "r"(b1))

#define CP_ASYNC16(dst, src)                                                   \
    asm volatile("cp.async.cg.shared.global [%0], [%1], 16;"                   \
                 :: "r"(dst), "l"(src) : "memory")
#define CP_COMMIT() asm volatile("cp.async.commit_group;" ::: "memory")
#define CP_WAIT1()  asm volatile("cp.async.wait_group 1;" ::: "memory")
#define CP_WAIT0()  asm volatile("cp.async.wait_group 0;" ::: "memory")

__device__ __forceinline__ unsigned pack2h(float a, float b) {
    __half2 h = __floats2half2_rn(a, b);
    return *reinterpret_cast<unsigned*>(&h);
}

// ---------------------------------------------------------------------------
// Relative-position bucket (exact integer reformulation of the reference)
// ---------------------------------------------------------------------------
__device__ __forceinline__ int rel_bucket(int rel) {
    int ret = (rel > 0) ? 16 : 0;
    int rp  = (rel < 0) ? -rel : rel;
    int off;
    if (rp < 8) {
        off = rp;
    } else {
        off = 8 + (rp >= 12) + (rp >= 16) + (rp >= 23) + (rp >= 32)
                + (rp >= 46) + (rp >= 64) + (rp >= 91);
    }
    return ret + off;
}

// ---------------------------------------------------------------------------
// pos_bias writer (float4 stores) — runs on forked stream, concurrent w/ GEMMs
// ---------------------------------------------------------------------------
__global__ __launch_bounds__(256) void bias_kernel(const float* __restrict__ tbl,
                                                   float* __restrict__ outb) {
    __shared__ float tcol[32];
    const int q = blockIdx.x;
    const int h = blockIdx.y;
    if (threadIdx.x < 32) tcol[threadIdx.x] = tbl[threadIdx.x * NHEADS + h];
    __syncthreads();
    float4* row = (float4*)(outb + ((size_t)h * S_LEN + q) * S_LEN);
#pragma unroll
    for (int it = 0; it < 2; it++) {
        int k4 = threadIdx.x + it * 256;
        int k = k4 * 4;
        float4 v = make_float4(tcol[rel_bucket(k - q)],
                               tcol[rel_bucket(k + 1 - q)],
                               tcol[rel_bucket(k + 2 - q)],
                               tcol[rel_bucket(k + 3 - q)]);
        row[k4] = v;
    }
}

// ---------------------------------------------------------------------------
// ALL conversions in one launch:
//   blocks [0, 8192): X -> fp16 hi/lo split (float4 per thread)
//   blocks [8192, 12288): 4x weight transpose+split (1024 blocks each)
// ---------------------------------------------------------------------------
__global__ __launch_bounds__(256) void conv_all(
    const float* __restrict__ X,  __half* __restrict__ xh,  __half* __restrict__ xl,
    const float* __restrict__ Wq, __half* __restrict__ wqh, __half* __restrict__ wql,
    const float* __restrict__ Wk, __half* __restrict__ wkh, __half* __restrict__ wkl,
    const float* __restrict__ Wv, __half* __restrict__ wvh, __half* __restrict__ wvl,
    const float* __restrict__ Wo, __half* __restrict__ woh, __half* __restrict__ wol) {
    const int tid = threadIdx.x;
    if (blockIdx.x < 8192) {
        int idx = blockIdx.x * 256 + tid;
        float4 v = ((const float4*)X)[idx];
        __half h0 = __float2half_rn(v.x), h1 = __float2half_rn(v.y);
        __half h2 = __float2half_rn(v.z), h3 = __float2half_rn(v.w);
        unsigned* H = (unsigned*)xh;
        unsigned* L = (unsigned*)xl;
        H[idx * 2]     = pack2h(v.x, v.y);
        H[idx * 2 + 1] = pack2h(v.z, v.w);
        L[idx * 2]     = pack2h(v.x - __half2float(h0), v.y - __half2float(h1));
        L[idx * 2 + 1] = pack2h(v.z - __half2float(h2), v.w - __half2float(h3));
        return;
    }
    __shared__ float t[32][33];
    const int wi = blockIdx.x - 8192;
    const float* W;
    __half *Th, *Tl;
    switch (wi >> 10) {
        case 0:  W = Wq; Th = wqh; Tl = wql; break;
        case 1:  W = Wk; Th = wkh; Tl = wkl; break;
        case 2:  W = Wv; Th = wvh; Tl = wvl; break;
        default: W = Wo; Th = woh; Tl = wol; break;
    }
    const int b  = wi & 1023;
    const int nb = (b & 31) * 32, kb = (b >> 5) * 32;
    const int tx = tid & 31, ty = tid >> 5;
#pragma unroll
    for (int r = ty; r < 32; r += 8)
        t[r][tx] = W[(size_t)(kb + r) * DMODEL + nb + tx];
    __syncthreads();
#pragma unroll
    for (int r = ty; r < 32; r += 8) {
        float v = t[tx][r];  // = W[kb+tx][nb+r]
        __half h = __float2half_rn(v);
        Th[(size_t)(nb + r) * DMODEL + kb + tx] = h;
        Tl[(size_t)(nb + r) * DMODEL + kb + tx] =
            __float2half_rn(v - __half2float(h));
    }
}

// ---------------------------------------------------------------------------
// HMMA fp16 GEMM, templated:
//   SPLIT==3: C = AhBh + AhBl + AlBh   SPLIT==1: C = AhBh
//   OUTM: 0 -> float C; 1 -> fp16 hi/lo pair; 2 -> fp16 single
// 128x128 CTA tile, BK=32, 4 warps @ 64x64, 2-stage cp.async, 2 CTAs/SM.
// ---------------------------------------------------------------------------
#define ROWB 80                               // 32 fp16 (64B) + 16B pad
#define MATB (128 * ROWB)                     // 10240 B

template<int SPLIT, int OUTM>
__global__ __launch_bounds__(128)
void gemm_h(const __half* __restrict__ Ah, const __half* __restrict__ Al,
            const __half* __restrict__ Bh, const __half* __restrict__ Bl,
            float* __restrict__ Cf, __half* __restrict__ Ch,
            __half* __restrict__ Cl, int M, int N, int K) {
    constexpr int NMATS = (SPLIT == 3) ? 4 : 2;
    constexpr int STAGEB = NMATS * MATB;
    extern __shared__ char smx[];
    const unsigned sb = smem_u32(smx);
    const int tid  = threadIdx.x;
    const int wid  = tid >> 5;
    const int lane = tid & 31;
    const int m0 = blockIdx.y * 128, n0 = blockIdx.x * 128;
    const int wm = (wid & 1) * 64;
    const int wn = (wid >> 1) * 64;

    // mat order: 0=Ah, 1=Bh, 2=Al, 3=Bl
    const __half* srcs[4];
    srcs[0] = Ah + (size_t)m0 * K;
    srcs[1] = Bh + (size_t)n0 * K;
    srcs[2] = (SPLIT == 3) ? (Al + (size_t)m0 * K) : srcs[0];
    srcs[3] = (SPLIT == 3) ? (Bl + (size_t)n0 * K) : srcs[1];

    const int ldrow = tid >> 2;               // 0..31
    const int ldch  = tid & 3;                // 16B chunk (4 per 64B row)

    const unsigned a_off = (unsigned)((lane & 15) * ROWB + (lane >> 4) * 16);
    const unsigned b_off = (unsigned)((((lane >> 4) << 3) + (lane & 7)) * ROWB
                                      + ((lane >> 3) & 1) * 16);

    float acc[4][8][4];
#pragma unroll
    for (int i = 0; i < 4; i++)
#pragma unroll
        for (int j = 0; j < 8; j++)
#pragma unroll
            for (int r = 0; r < 4; r++) acc[i][j][r] = 0.0f;

    const int NIT = K / 32;

    auto load_stage = [&](int s, int kit) {
        const int k0 = kit * 32;
        unsigned dbase = sb + (unsigned)(s * STAGEB);
#pragma unroll
        for (int mtx = 0; mtx < NMATS; mtx++) {
#pragma unroll
            for (int i = 0; i < 4; i++) {
                int row = ldrow + i * 32;
                unsigned dst = dbase + (unsigned)(mtx * MATB + row * ROWB + ldch * 16);
                const char* src = (const char*)(srcs[mtx] + k0 + (size_t)row * K)
                                + ldch * 16;
                CP_ASYNC16(dst, src);
            }
        }
    };

    load_stage(0, 0);
    CP_COMMIT();

    for (int kit = 0; kit < NIT; kit++) {
        if (kit + 1 < NIT) {
            load_stage((kit + 1) & 1, kit + 1);
            CP_COMMIT();
            CP_WAIT1();
        } else {
            CP_WAIT0();
        }
        __syncthreads();

        const unsigned tb = sb + (unsigned)((kit & 1) * STAGEB);
#pragma unroll
        for (int kk = 0; kk < 32; kk += 16) {
            constexpr int NSP = (SPLIT == 3) ? 2 : 1;
            unsigned afr[NSP][4][4];
            unsigned bfr[NSP][4][4];
#pragma unroll
            for (int sp = 0; sp < NSP; sp++) {
#pragma unroll
                for (int mt = 0; mt < 4; mt++) {
                    unsigned ad = tb + (unsigned)(sp * 2 * MATB) + a_off
                                + (unsigned)((wm + mt * 16) * ROWB + kk * 2);
                    LDMATRIX_X4(afr[sp][mt][0], afr[sp][mt][1],
                                afr[sp][mt][2], afr[sp][mt][3], ad);
                }
#pragma unroll
                for (int nt = 0; nt < 4; nt++) {
                    unsigned bd = tb + (unsigned)((1 + sp * 2) * MATB) + b_off
                                + (unsigned)((wn + nt * 16) * ROWB + kk * 2);
                    LDMATRIX_X4(bfr[sp][nt][0], bfr[sp][nt][1],
                                bfr[sp][nt][2], bfr[sp][nt][3], bd);
                }
            }
#pragma unroll
            for (int mt = 0; mt < 4; mt++) {
#pragma unroll
                for (int n8 = 0; n8 < 8; n8++) {
                    const int pr = n8 >> 1, hf = (n8 & 1) * 2;
                    unsigned bh0 = bfr[0][pr][hf], bh1 = bfr[0][pr][hf + 1];
                    MMAF16(acc[mt][n8], afr[0][mt][0], afr[0][mt][1],
                           afr[0][mt][2], afr[0][mt][3], bh0, bh1);
                    if (SPLIT == 3) {
                        unsigned bl0 = bfr[1][pr][hf], bl1 = bfr[1][pr][hf + 1];
                        MMAF16(acc[mt][n8], afr[0][mt][0], afr[0][mt][1],
                               afr[0][mt][2], afr[0][mt][3], bl0, bl1);
                        MMAF16(acc[mt][n8], afr[1][mt][0], afr[1][mt][1],
                               afr[1][mt][2], afr[1][mt][3], bh0, bh1);
                    }
                }
            }
        }
        __syncthreads();
    }

    // ---- epilogue ----
    const int r0 = lane >> 2, c0 = (lane & 3) * 2;
#pragma unroll
    for (int mt = 0; mt < 4; mt++) {
#pragma unroll
        for (int n8 = 0; n8 < 8; n8++) {
            int row = m0 + wm + mt * 16 + r0;
            int col = n0 + wn + n8 * 8 + c0;
            float v0 = acc[mt][n8][0], v1 = acc[mt][n8][1];
            float v2 = acc[mt][n8][2], v3 = acc[mt][n8][3];
            if (OUTM == 0) {
                float* Cp = Cf + (size_t)row * N + col;
                *(float2*)Cp = make_float2(v0, v1);
                *(float2*)(Cp + (size_t)8 * N) = make_float2(v2, v3);
            } else if (OUTM == 2) {
                *(unsigned*)(Ch + (size_t)row * N + col) = pack2h(v0, v1);
                *(unsigned*)(Ch + (size_t)(row + 8) * N + col) = pack2h(v2, v3);
            } else {
                __half h0 = __float2half_rn(v0), h1 = __float2half_rn(v1);
                __half h2 = __float2half_rn(v2), h3 = __float2half_rn(v3);
                *(unsigned*)(Ch + (size_t)row * N + col) =
                    *(unsigned*)&h0 | (*(unsigned*)&h1 << 16);
                *(unsigned*)(Ch + (size_t)(row + 8) * N + col) =
                    *(unsigned*)&h2 | (*(unsigned*)&h3 << 16);
                *(unsigned*)(Cl + (size_t)row * N + col) =
                    pack2h(v0 - __half2float(h0), v1 - __half2float(h1));
                *(unsigned*)(Cl + (size_t)(row + 8) * N + col) =
                    pack2h(v2 - __half2float(h2), v3 - __half2float(h3));
            }
        }
    }
}

// ---------------------------------------------------------------------------
// HMMA flash attention: 128q x 128k tiles, 8 warps (16 q-rows each).
// QK split-fp16 (3 MMAs), PV single fp16 via fragment chaining + ldmatrix.trans.
// ---------------------------------------------------------------------------
#define FPITCH 144
#define FMAT (128 * FPITCH)                   // 18432
#define FSTAGE (3 * FMAT)                     // Kh, Kl, V
#define FQOFF (2 * FSTAGE)                    // 110592
#define FLASH_SMEM (FQOFF + 2 * FMAT)         // 147456

__device__ __forceinline__ void load_tile_f(unsigned sdst, const __half* g, int tid) {
#pragma unroll
    for (int i = 0; i < 4; i++) {
        int c = tid + i * 256;
        int row = c >> 3, ch = c & 7;
        CP_ASYNC16(sdst + (unsigned)(row * FPITCH + ch * 16),
                   g + (size_t)row * DMODEL + ch * 8);
    }
}

__global__ __launch_bounds__(256, 1)
void flash_hmma(const __half* __restrict__ Qh, const __half* __restrict__ Ql,
                const __half* __restrict__ Kh, const __half* __restrict__ Kl,
                const __half* __restrict__ Vf, const float* __restrict__ tbl,
                __half* __restrict__ Oh) {
    extern __shared__ char sm[];
    __shared__ float tcol[32];
    __shared__ float bias183[184];
    const unsigned sb = smem_u32(sm);
    const int tid = threadIdx.x, wid = tid >> 5, lane = tid & 31;
    const int q0 = blockIdx.x * 128, h = blockIdx.y, b = blockIdx.z;

    const size_t qbase = ((size_t)(b * S_LEN + q0)) * DMODEL + h * DKV;
    const size_t kbase = ((size_t)(b * S_LEN)) * DMODEL + h * DKV;

    // group 0: Q (hi+lo) + tile 0 (Kh, Kl, V)
    load_tile_f(sb + FQOFF, Qh + qbase, tid);
    load_tile_f(sb + FQOFF + FMAT, Ql + qbase, tid);
    load_tile_f(sb, Kh + kbase, tid);
    load_tile_f(sb + FMAT, Kl + kbase, tid);
    load_tile_f(sb + 2 * FMAT, Vf + kbase, tid);
    CP_COMMIT();

    if (tid < 32) tcol[tid] = tbl[tid * NHEADS + h];
    __syncthreads();
    if (tid < 183) bias183[tid] = tcol[rel_bucket(tid - 91)];

    const int u = lane & 3, g = lane >> 2;
    const int qA = q0 + wid * 16 + g;     // global q row of c0/c1
    const int qB = qA + 8;                // global q row of c2/c3

    const unsigned aoff = (unsigned)((lane & 15) * FPITCH + (lane >> 4) * 16);
    const unsigned boff = (unsigned)(((((lane >> 4) << 3) | (lane & 7)) * FPITCH)
                                     + ((lane >> 3) & 1) * 16);
    const unsigned voff = (unsigned)(((((lane >> 3) & 1) * 8 + (lane & 7)) * FPITCH)
                                     + (lane >> 4) * 16);

    unsigned aqh[4][4], aql[4][4];
    float accO[8][4];
#pragma unroll
    for (int i = 0; i < 8; i++)
#pragma unroll
        for (int j = 0; j < 4; j++) accO[i][j] = 0.0f;
    float mA = -1e30f, mB = -1e30f, lA = 0.0f, lB = 0.0f;

    for (int t = 0; t < 16; t++) {
        if (t + 1 < 16) {
            unsigned st = sb + (unsigned)(((t + 1) & 1) * FSTAGE);
            size_t kb2 = kbase + (size_t)(t + 1) * 128 * DMODEL;
            load_tile_f(st, Kh + kb2, tid);
            load_tile_f(st + FMAT, Kl + kb2, tid);
            load_tile_f(st + 2 * FMAT, Vf + kb2, tid);
            CP_COMMIT();
            CP_WAIT1();
        } else {
            CP_WAIT0();
        }
        __syncthreads();

        if (t == 0) {
            // build Q register fragments (m16 x k64, hi and lo)
#pragma unroll
            for (int c = 0; c < 4; c++) {
                unsigned qa = sb + FQOFF + (unsigned)(wid * 16 * FPITCH) + aoff
                            + (unsigned)(c * 32);
                LDMATRIX_X4(aqh[c][0], aqh[c][1], aqh[c][2], aqh[c][3], qa);
                LDMATRIX_X4(aql[c][0], aql[c][1], aql[c][2], aql[c][3], qa + FMAT);
            }
        }

        const unsigned stg = sb + (unsigned)((t & 1) * FSTAGE);

        // ---- S = Q K^T (split fp16, f32 accum) ----
        float accS[16][4];
#pragma unroll
        for (int i = 0; i < 16; i++)
#pragma unroll
            for (int j = 0; j < 4; j++) accS[i][j] = 0.0f;

#pragma unroll
        for (int c = 0; c < 4; c++) {
#pragma unroll
            for (int gg = 0; gg < 8; gg++) {
                unsigned bh0, bh1, bh2, bh3, bl0, bl1, bl2, bl3;
                unsigned ka = stg + boff + (unsigned)(gg * 16 * FPITCH + c * 32);
                LDMATRIX_X4(bh0, bh1, bh2, bh3, ka);
                LDMATRIX_X4(bl0, bl1, bl2, bl3, ka + FMAT);
                MMAF16(accS[2 * gg], aqh[c][0], aqh[c][1], aqh[c][2], aqh[c][3], bh0, bh1);
                MMAF16(accS[2 * gg + 1], aqh[c][0], aqh[c][1], aqh[c][2], aqh[c][3], bh2, bh3);
                MMAF16(accS[2 * gg], aqh[c][0], aqh[c][1], aqh[c][2], aqh[c][3], bl0, bl1);
                MMAF16(accS[2 * gg + 1], aqh[c][0], aqh[c][1], aqh[c][2], aqh[c][3], bl2, bl3);
                MMAF16(accS[2 * gg], aql[c][0], aql[c][1], aql[c][2], aql[c][3], bh0, bh1);
                MMAF16(accS[2 * gg + 1], aql[c][0], aql[c][1], aql[c][2], aql[c][3], bh2, bh3);
            }
        }

        // ---- bias + online softmax ----
        const int k0 = t * 128;
        float tmA = -1e30f, tmB = -1e30f;
#pragma unroll
        for (int s8 = 0; s8 < 16; s8++) {
            int kc = k0 + s8 * 8 + 2 * u;
            int iA0 = min(max(kc - qA, -91), 91) + 91;
            int iA1 = min(max(kc + 1 - qA, -91), 91) + 91;
            int iB0 = min(max(kc - qB, -91), 91) + 91;
            int iB1 = min(max(kc + 1 - qB, -91), 91) + 91;
            accS[s8][0] += bias183[iA0];
            accS[s8][1] += bias183[iA1];
            accS[s8][2] += bias183[iB0];
            accS[s8][3] += bias183[iB1];
            tmA = fmaxf(tmA, fmaxf(accS[s8][0], accS[s8][1]));
            tmB = fmaxf(tmB, fmaxf(accS[s8][2], accS[s8][3]));
        }
        tmA = fmaxf(tmA, __shfl_xor_sync(0xffffffffu, tmA, 1));
        tmA = fmaxf(tmA, __shfl_xor_sync(0xffffffffu, tmA, 2));
        tmB = fmaxf(tmB, __shfl_xor_sync(0xffffffffu, tmB, 1));
        tmB = fmaxf(tmB, __shfl_xor_sync(0xffffffffu, tmB, 2));

        float nmA = fmaxf(mA, tmA), scA = __expf(mA - nmA);
        float nmB = fmaxf(mB, tmB), scB = __expf(mB - nmB);
        mA = nmA; mB = nmB;

        float sA = 0.0f, sB = 0.0f;
#pragma unroll
        for (int s8 = 0; s8 < 16; s8++) {
            accS[s8][0] = __expf(accS[s8][0] - nmA);
            accS[s8][1] = __expf(accS[s8][1] - nmA);
            accS[s8][2] = __expf(accS[s8][2] - nmB);
            accS[s8][3] = __expf(accS[s8][3] - nmB);
            sA += accS[s8][0] + accS[s8][1];
            sB += accS[s8][2] + accS[s8][3];
        }
        sA += __shfl_xor_sync(0xffffffffu, sA, 1);
        sA += __shfl_xor_sync(0xffffffffu, sA, 2);
        sB += __shfl_xor_sync(0xffffffffu, sB, 1);
        sB += __shfl_xor_sync(0xffffffffu, sB, 2);
        lA = lA * scA + sA;
        lB = lB * scB + sB;

#pragma unroll
        for (int nt = 0; nt < 8; nt++) {
            accO[nt][0] *= scA; accO[nt][1] *= scA;
            accO[nt][2] *= scB; accO[nt][3] *= scB;
        }

        // ---- O += P V (fragment chaining, fp16 P & V) ----
#pragma unroll
        for (int j = 0; j < 8; j++) {
            unsigned a0 = pack2h(accS[2 * j][0], accS[2 * j][1]);
            unsigned a1 = pack2h(accS[2 * j][2], accS[2 * j][3]);
            unsigned a2 = pack2h(accS[2 * j + 1][0], accS[2 * j + 1][1]);
            unsigned a3 = pack2h(accS[2 * j + 1][2], accS[2 * j + 1][3]);
#pragma unroll
            for (int g2 = 0; g2 < 4; g2++) {
                unsigned bv0, bv1, bv2, bv3;
                unsigned va = stg + (unsigned)(2 * FMAT) + voff
                            + (unsigned)(j * 16 * FPITCH + g2 * 32);
                LDMATRIX_X4_T(bv0, bv1, bv2, bv3, va);
                MMAF16(accO[2 * g2], a0, a1, a2, a3, bv0, bv1);
                MMAF16(accO[2 * g2 + 1], a0, a1, a2, a3, bv2, bv3);
            }
        }
        __syncthreads();
    }

    // ---- epilogue: normalize, write fp16 ----
    const float iA = 1.0f / lA, iB = 1.0f / lB;
    const size_t rowA = (size_t)(b * S_LEN + qA) * DMODEL + h * DKV;
    const size_t rowB = (size_t)(b * S_LEN + qB) * DMODEL + h * DKV;
#pragma unroll
    for (int nt = 0; nt < 8; nt++) {
        int col = nt * 8 + 2 * u;
        *(unsigned*)(Oh + rowA + col) = pack2h(accO[nt][0] * iA, accO[nt][1] * iA);
        *(unsigned*)(Oh + rowB + col) = pack2h(accO[nt][2] * iB, accO[nt][3] * iB);
    }
}

// ---------------------------------------------------------------------------
extern "C" void kernel_launch(void* const* d_in, const int* in_sizes, int n_in,
                              void* d_out, int out_size) {
    const float* X   = (const float*)d_in[0];
    const float* Wq  = (const float*)d_in[1];
    const float* Wk  = (const float*)d_in[2];
    const float* Wv  = (const float*)d_in[3];
    const float* Wo  = (const float*)d_in[4];
    const float* tbl = (const float*)d_in[5];
    float* out = (float*)d_out;

    __half *xh, *xl, *wqh, *wql, *wkh, *wkl, *wvh, *wvl, *woh, *wol;
    __half *qh, *ql, *kh, *kl, *vh, *oh;
    cudaGetSymbolAddress((void**)&xh, g_xh);
    cudaGetSymbolAddress((void**)&xl, g_xl);
    cudaGetSymbolAddress((void**)&wqh, g_wqh);
    cudaGetSymbolAddress((void**)&wql, g_wql);
    cudaGetSymbolAddress((void**)&wkh, g_wkh);
    cudaGetSymbolAddress((void**)&wkl, g_wkl);
    cudaGetSymbolAddress((void**)&wvh, g_wvh);
    cudaGetSymbolAddress((void**)&wvl, g_wvl);
    cudaGetSymbolAddress((void**)&woh, g_woh);
    cudaGetSymbolAddress((void**)&wol, g_wol);
    cudaGetSymbolAddress((void**)&qh, g_qh);
    cudaGetSymbolAddress((void**)&ql, g_ql);
    cudaGetSymbolAddress((void**)&kh, g_kh);
    cudaGetSymbolAddress((void**)&kl, g_kl);
    cudaGetSymbolAddress((void**)&vh, g_vh);
    cudaGetSymbolAddress((void**)&oh, g_oh);

    // One-time side stream + events for the pos_bias fork (created on the
    // first, non-captured correctness call; reused — identical work per call).
    static cudaStream_t s2 = nullptr;
    static cudaEvent_t evFork = nullptr, evJoin = nullptr;
    if (s2 == nullptr) {
        cudaStreamCreateWithFlags(&s2, cudaStreamNonBlocking);
        cudaEventCreateWithFlags(&evFork, cudaEventDisableTiming);
        cudaEventCreateWithFlags(&evJoin, cudaEventDisableTiming);
    }

    // ---- fork: pos_bias on side stream, concurrent with the main pipeline ----
    cudaEventRecord(evFork, 0);
    cudaStreamWaitEvent(s2, evFork, 0);
    {
        dim3 bg(S_LEN, NHEADS);
        bias_kernel<<<bg, 256, 0, s2>>>(tbl, out + OUT_ELEMS);
    }
    cudaEventRecord(evJoin, s2);

    // ---- main stream ----
    // 0: all conversions (X split + 4 weight transposes)
    conv_all<<<12288, 256>>>(X, xh, xl, Wq, wqh, wql, Wk, wkh, wkl,
                             Wv, wvh, wvl, Wo, woh, wol);

    dim3 gg(DMODEL / 128, M_ROWS / 128);

    // 1-2: Q, K projections (split, fp16 hi/lo outputs)
    cudaFuncSetAttribute(gemm_h<3, 1>, cudaFuncAttributeMaxDynamicSharedMemorySize,
                         2 * 4 * MATB);
    gemm_h<3, 1><<<gg, 128, 2 * 4 * MATB>>>(xh, xl, wqh, wql,
                                            nullptr, qh, ql,
                                            M_ROWS, DMODEL, DMODEL);
    gemm_h<3, 1><<<gg, 128, 2 * 4 * MATB>>>(xh, xl, wkh, wkl,
                                            nullptr, kh, kl,
                                            M_ROWS, DMODEL, DMODEL);

    // 3: V projection (single-pass fp16)
    cudaFuncSetAttribute(gemm_h<1, 2>, cudaFuncAttributeMaxDynamicSharedMemorySize,
                         2 * 2 * MATB);
    gemm_h<1, 2><<<gg, 128, 2 * 2 * MATB>>>(xh, nullptr, wvh, nullptr,
                                            nullptr, vh, nullptr,
                                            M_ROWS, DMODEL, DMODEL);

    // 4: flash attention (HMMA)
    cudaFuncSetAttribute(flash_hmma, cudaFuncAttributeMaxDynamicSharedMemorySize,
                         FLASH_SMEM);
    dim3 fg(S_LEN / 128, NHEADS, BATCH);
    flash_hmma<<<fg, 256, FLASH_SMEM>>>(qh, ql, kh, kl, vh, tbl, oh);

    // 5: output projection (single-pass fp16, f32 out)
    cudaFuncSetAttribute(gemm_h<1, 0>, cudaFuncAttributeMaxDynamicSharedMemorySize,
                         2 * 2 * MATB);
    gemm_h<1, 0><<<gg, 128, 2 * 2 * MATB>>>(oh, nullptr, woh, nullptr,
                                            out, nullptr, nullptr,
                                            M_ROWS, DMODEL, DMODEL);

    // ---- join: pos_bias must complete before kernel_launch's work is done ----
    cudaStreamWaitEvent(0, evJoin, 0);
}

// round 7
// speedup vs baseline: 5.3513x; 1.0137x over previous
#include <cuda_runtime.h>
#include <cuda_fp16.h>
#include <math.h>

// Problem constants (fixed shapes)
#define S_LEN   2048
#define BATCH   4
#define NHEADS  16
#define DKV     64
#define DMODEL  1024
#define M_ROWS  (BATCH * S_LEN)                 // 8192
#define OUT_ELEMS  (M_ROWS * DMODEL)            // 8388608
#define BIAS_ELEMS (NHEADS * S_LEN * S_LEN)     // 67108864

// ---------------------------------------------------------------------------
// Device scratch (fp16 everywhere)
// ---------------------------------------------------------------------------
__device__ __half g_xh[M_ROWS * DMODEL];
__device__ __half g_xl[M_ROWS * DMODEL];
__device__ __half g_wqh[DMODEL * DMODEL];
__device__ __half g_wql[DMODEL * DMODEL];
__device__ __half g_wkh[DMODEL * DMODEL];
__device__ __half g_wkl[DMODEL * DMODEL];
__device__ __half g_wvh[DMODEL * DMODEL];
__device__ __half g_wvl[DMODEL * DMODEL];
__device__ __half g_woh[DMODEL * DMODEL];
__device__ __half g_wol[DMODEL * DMODEL];
__device__ __half g_qh[M_ROWS * DMODEL];
__device__ __half g_ql[M_ROWS * DMODEL];
__device__ __half g_kh[M_ROWS * DMODEL];
__device__ __half g_kl[M_ROWS * DMODEL];
__device__ __half g_vh[M_ROWS * DMODEL];
__device__ __half g_oh[M_ROWS * DMODEL];

// ---------------------------------------------------------------------------
// PTX helpers (sm_80-level only)
// ---------------------------------------------------------------------------
__device__ __forceinline__ unsigned smem_u32(const void* p) {
    unsigned a;
    asm("{ .reg .u64 t; cvta.to.shared.u64 t, %1; cvt.u32.u64 %0, t; }"
        : "=r"(a) : "l"(p));
    return a;
}

#define LDMATRIX_X4(r0, r1, r2, r3, addr)                                      \
    asm volatile("ldmatrix.sync.aligned.m8n8.x4.shared.b16 {%0,%1,%2,%3}, [%4];" \
                 : "=r"(r0), "=r"(r1), "=r"(r2), "=r"(r3) : "r"(addr))

#define LDMATRIX_X4_T(r0, r1, r2, r3, addr)                                    \
    asm volatile("ldmatrix.sync.aligned.m8n8.x4.trans.shared.b16 {%0,%1,%2,%3}, [%4];" \
                 : "=r"(r0), "=r"(r1), "=r"(r2), "=r"(r3) : "r"(addr))

#define MMAF16(d, a0, a1, a2, a3, b0, b1)                                      \
    asm volatile("mma.sync.aligned.m16n8k16.row.col.f32.f16.f16.f32 "          \
                 "{%0,%1,%2,%3},{%4,%5,%6,%7},{%8,%9},{%0,%1,%2,%3};"          \
                 : "+f"((d)[0]), "+f"((d)[1]), "+f"((d)[2]), "+f"((d)[3])      \
                 : "r"(a0), "r"(a1), "r"(a2), "r"(a3), "r"(b0), "r"(b1))

#define CP_ASYNC16(dst, src)                                                   \
    asm volatile("cp.async.cg.shared.global [%0], [%1], 16;"                   \
                 :: "r"(dst), "l"(src) : "memory")
#define CP_COMMIT() asm volatile("cp.async.commit_group;" ::: "memory")
#define CP_WAIT1()  asm volatile("cp.async.wait_group 1;" ::: "memory")
#define CP_WAIT0()  asm volatile("cp.async.wait_group 0;" ::: "memory")

__device__ __forceinline__ unsigned pack2h(float a, float b) {
    __half2 h = __floats2half2_rn(a, b);
    return *reinterpret_cast<unsigned*>(&h);
}

// ---------------------------------------------------------------------------
// Relative-position bucket (exact integer reformulation of the reference)
// ---------------------------------------------------------------------------
__device__ __forceinline__ int rel_bucket(int rel) {
    int ret = (rel > 0) ? 16 : 0;
    int rp  = (rel < 0) ? -rel : rel;
    int off;
    if (rp < 8) {
        off = rp;
    } else {
        off = 8 + (rp >= 12) + (rp >= 16) + (rp >= 23) + (rp >= 32)
                + (rp >= 46) + (rp >= 64) + (rp >= 91);
    }
    return ret + off;
}

// ---------------------------------------------------------------------------
// pos_bias writer (float4 stores) — runs on forked stream
// ---------------------------------------------------------------------------
__global__ __launch_bounds__(256) void bias_kernel(const float* __restrict__ tbl,
                                                   float* __restrict__ outb) {
    __shared__ float tcol[32];
    const int q = blockIdx.x;
    const int h = blockIdx.y;
    if (threadIdx.x < 32) tcol[threadIdx.x] = tbl[threadIdx.x * NHEADS + h];
    __syncthreads();
    float4* row = (float4*)(outb + ((size_t)h * S_LEN + q) * S_LEN);
#pragma unroll
    for (int it = 0; it < 2; it++) {
        int k4 = threadIdx.x + it * 256;
        int k = k4 * 4;
        float4 v = make_float4(tcol[rel_bucket(k - q)],
                               tcol[rel_bucket(k + 1 - q)],
                               tcol[rel_bucket(k + 2 - q)],
                               tcol[rel_bucket(k + 3 - q)]);
        row[k4] = v;
    }
}

// ---------------------------------------------------------------------------
// ALL conversions in one launch
// ---------------------------------------------------------------------------
__global__ __launch_bounds__(256) void conv_all(
    const float* __restrict__ X,  __half* __restrict__ xh,  __half* __restrict__ xl,
    const float* __restrict__ Wq, __half* __restrict__ wqh, __half* __restrict__ wql,
    const float* __restrict__ Wk, __half* __restrict__ wkh, __half* __restrict__ wkl,
    const float* __restrict__ Wv, __half* __restrict__ wvh, __half* __restrict__ wvl,
    const float* __restrict__ Wo, __half* __restrict__ woh, __half* __restrict__ wol) {
    const int tid = threadIdx.x;
    if (blockIdx.x < 8192) {
        int idx = blockIdx.x * 256 + tid;
        float4 v = ((const float4*)X)[idx];
        __half h0 = __float2half_rn(v.x), h1 = __float2half_rn(v.y);
        __half h2 = __float2half_rn(v.z), h3 = __float2half_rn(v.w);
        unsigned* H = (unsigned*)xh;
        unsigned* L = (unsigned*)xl;
        H[idx * 2]     = pack2h(v.x, v.y);
        H[idx * 2 + 1] = pack2h(v.z, v.w);
        L[idx * 2]     = pack2h(v.x - __half2float(h0), v.y - __half2float(h1));
        L[idx * 2 + 1] = pack2h(v.z - __half2float(h2), v.w - __half2float(h3));
        return;
    }
    __shared__ float t[32][33];
    const int wi = blockIdx.x - 8192;
    const float* W;
    __half *Th, *Tl;
    switch (wi >> 10) {
        case 0:  W = Wq; Th = wqh; Tl = wql; break;
        case 1:  W = Wk; Th = wkh; Tl = wkl; break;
        case 2:  W = Wv; Th = wvh; Tl = wvl; break;
        default: W = Wo; Th = woh; Tl = wol; break;
    }
    const int b  = wi & 1023;
    const int nb = (b & 31) * 32, kb = (b >> 5) * 32;
    const int tx = tid & 31, ty = tid >> 5;
#pragma unroll
    for (int r = ty; r < 32; r += 8)
        t[r][tx] = W[(size_t)(kb + r) * DMODEL + nb + tx];
    __syncthreads();
#pragma unroll
    for (int r = ty; r < 32; r += 8) {
        float v = t[tx][r];  // = W[kb+tx][nb+r]
        __half h = __float2half_rn(v);
        Th[(size_t)(nb + r) * DMODEL + kb + tx] = h;
        Tl[(size_t)(nb + r) * DMODEL + kb + tx] =
            __float2half_rn(v - __half2float(h));
    }
}

// ---------------------------------------------------------------------------
// HMMA fp16 GEMM:
//   SPLIT==3: C = AhBh + AhBl + AlBh   SPLIT==1: C = AhBh
//   OUTM: 0 -> float C; 1 -> fp16 hi/lo pair; 2 -> fp16 single
// CTA tile 64(M)x128(N), BK=32, 4 warps @ 32x64, 2-stage cp.async,
// 3 (split) / 4 (single) CTAs per SM for barrier-phase diversity.
// ---------------------------------------------------------------------------
#define ROWB 80                               // 32 fp16 (64B) + 16B pad
#define A_MATB (64 * ROWB)                    // 5120 B
#define B_MATB (128 * ROWB)                   // 10240 B

template<int SPLIT, int OUTM>
__global__ __launch_bounds__(128, (SPLIT == 3) ? 3 : 4)
void gemm_h(const __half* __restrict__ Ah, const __half* __restrict__ Al,
            const __half* __restrict__ Bh, const __half* __restrict__ Bl,
            float* __restrict__ Cf, __half* __restrict__ Ch,
            __half* __restrict__ Cl, int M, int N, int K) {
    constexpr int NSP = (SPLIT == 3) ? 2 : 1;
    constexpr int STAGEB = NSP * (A_MATB + B_MATB);
    constexpr int BOFF = NSP * A_MATB;
    extern __shared__ char smx[];
    const unsigned sb = smem_u32(smx);
    const int tid  = threadIdx.x;
    const int wid  = tid >> 5;
    const int lane = tid & 31;
    const int m0 = blockIdx.y * 64, n0 = blockIdx.x * 128;
    const int wm = (wid & 1) * 32;
    const int wn = (wid >> 1) * 64;

    const __half* aS[2];
    const __half* bS[2];
    aS[0] = Ah + (size_t)m0 * K;
    bS[0] = Bh + (size_t)n0 * K;
    aS[1] = (SPLIT == 3) ? (Al + (size_t)m0 * K) : aS[0];
    bS[1] = (SPLIT == 3) ? (Bl + (size_t)n0 * K) : bS[0];

    const int ldrow = tid >> 2;               // 0..31
    const int ldch  = tid & 3;                // 16B chunk (4 per 64B row)

    const unsigned a_off = (unsigned)((lane & 15) * ROWB + (lane >> 4) * 16);
    const unsigned b_off = (unsigned)((((lane >> 4) << 3) + (lane & 7)) * ROWB
                                      + ((lane >> 3) & 1) * 16);

    float acc[2][8][4];
#pragma unroll
    for (int i = 0; i < 2; i++)
#pragma unroll
        for (int j = 0; j < 8; j++)
#pragma unroll
            for (int r = 0; r < 4; r++) acc[i][j][r] = 0.0f;

    const int NIT = K / 32;

    auto load_stage = [&](int s, int kit) {
        const int k0 = kit * 32;
        unsigned db = sb + (unsigned)(s * STAGEB);
#pragma unroll
        for (int sp = 0; sp < NSP; sp++) {
#pragma unroll
            for (int i = 0; i < 2; i++) {       // A: 64 rows
                int row = ldrow + i * 32;
                CP_ASYNC16(db + (unsigned)(sp * A_MATB + row * ROWB + ldch * 16),
                           aS[sp] + k0 + (size_t)row * K + ldch * 8);
            }
#pragma unroll
            for (int i = 0; i < 4; i++) {       // B: 128 rows
                int row = ldrow + i * 32;
                CP_ASYNC16(db + (unsigned)(BOFF + sp * B_MATB + row * ROWB + ldch * 16),
                           bS[sp] + k0 + (size_t)row * K + ldch * 8);
            }
        }
    };

    load_stage(0, 0);
    CP_COMMIT();

    for (int kit = 0; kit < NIT; kit++) {
        if (kit + 1 < NIT) {
            load_stage((kit + 1) & 1, kit + 1);
            CP_COMMIT();
            CP_WAIT1();
        } else {
            CP_WAIT0();
        }
        __syncthreads();

        const unsigned tb = sb + (unsigned)((kit & 1) * STAGEB);
#pragma unroll
        for (int kk = 0; kk < 32; kk += 16) {
            unsigned afr[NSP][2][4];
#pragma unroll
            for (int sp = 0; sp < NSP; sp++)
#pragma unroll
                for (int mt = 0; mt < 2; mt++) {
                    unsigned ad = tb + (unsigned)(sp * A_MATB) + a_off
                                + (unsigned)((wm + mt * 16) * ROWB + kk * 2);
                    LDMATRIX_X4(afr[sp][mt][0], afr[sp][mt][1],
                                afr[sp][mt][2], afr[sp][mt][3], ad);
                }
#pragma unroll
            for (int nt = 0; nt < 4; nt++) {
                unsigned bh[4], bl[4];
                unsigned bd = tb + (unsigned)BOFF + b_off
                            + (unsigned)((wn + nt * 16) * ROWB + kk * 2);
                LDMATRIX_X4(bh[0], bh[1], bh[2], bh[3], bd);
                if (SPLIT == 3) {
                    LDMATRIX_X4(bl[0], bl[1], bl[2], bl[3], bd + (unsigned)B_MATB);
                }
#pragma unroll
                for (int mt = 0; mt < 2; mt++) {
#pragma unroll
                    for (int h = 0; h < 2; h++) {
                        float* a = acc[mt][nt * 2 + h];
                        MMAF16(a, afr[0][mt][0], afr[0][mt][1],
                               afr[0][mt][2], afr[0][mt][3], bh[h * 2], bh[h * 2 + 1]);
                        if (SPLIT == 3) {
                            MMAF16(a, afr[0][mt][0], afr[0][mt][1],
                                   afr[0][mt][2], afr[0][mt][3], bl[h * 2], bl[h * 2 + 1]);
                            MMAF16(a, afr[1][mt][0], afr[1][mt][1],
                                   afr[1][mt][2], afr[1][mt][3], bh[h * 2], bh[h * 2 + 1]);
                        }
                    }
                }
            }
        }
        __syncthreads();
    }

    // ---- epilogue ----
    const int r0 = lane >> 2, c0 = (lane & 3) * 2;
#pragma unroll
    for (int mt = 0; mt < 2; mt++) {
#pragma unroll
        for (int n8 = 0; n8 < 8; n8++) {
            int row = m0 + wm + mt * 16 + r0;
            int col = n0 + wn + n8 * 8 + c0;
            float v0 = acc[mt][n8][0], v1 = acc[mt][n8][1];
            float v2 = acc[mt][n8][2], v3 = acc[mt][n8][3];
            if (OUTM == 0) {
                float* Cp = Cf + (size_t)row * N + col;
                *(float2*)Cp = make_float2(v0, v1);
                *(float2*)(Cp + (size_t)8 * N) = make_float2(v2, v3);
            } else if (OUTM == 2) {
                *(unsigned*)(Ch + (size_t)row * N + col) = pack2h(v0, v1);
                *(unsigned*)(Ch + (size_t)(row + 8) * N + col) = pack2h(v2, v3);
            } else {
                __half h0 = __float2half_rn(v0), h1 = __float2half_rn(v1);
                __half h2 = __float2half_rn(v2), h3 = __float2half_rn(v3);
                *(unsigned*)(Ch + (size_t)row * N + col) =
                    *(unsigned*)&h0 | (*(unsigned*)&h1 << 16);
                *(unsigned*)(Ch + (size_t)(row + 8) * N + col) =
                    *(unsigned*)&h2 | (*(unsigned*)&h3 << 16);
                *(unsigned*)(Cl + (size_t)row * N + col) =
                    pack2h(v0 - __half2float(h0), v1 - __half2float(h1));
                *(unsigned*)(Cl + (size_t)(row + 8) * N + col) =
                    pack2h(v2 - __half2float(h2), v3 - __half2float(h3));
            }
        }
    }
}

// ---------------------------------------------------------------------------
// HMMA flash attention: 128q x 128k tiles, 8 warps (16 q-rows each).
// QK split-fp16 (3 MMAs), PV single fp16 via fragment chaining + ldmatrix.trans.
// ---------------------------------------------------------------------------
#define FPITCH 144
#define FMAT (128 * FPITCH)                   // 18432
#define FSTAGE (3 * FMAT)                     // Kh, Kl, V
#define FQOFF (2 * FSTAGE)                    // 110592
#define FLASH_SMEM (FQOFF + 2 * FMAT)         // 147456

__device__ __forceinline__ void load_tile_f(unsigned sdst, const __half* g, int tid) {
#pragma unroll
    for (int i = 0; i < 4; i++) {
        int c = tid + i * 256;
        int row = c >> 3, ch = c & 7;
        CP_ASYNC16(sdst + (unsigned)(row * FPITCH + ch * 16),
                   g + (size_t)row * DMODEL + ch * 8);
    }
}

__global__ __launch_bounds__(256, 1)
void flash_hmma(const __half* __restrict__ Qh, const __half* __restrict__ Ql,
                const __half* __restrict__ Kh, const __half* __restrict__ Kl,
                const __half* __restrict__ Vf, const float* __restrict__ tbl,
                __half* __restrict__ Oh) {
    extern __shared__ char sm[];
    __shared__ float tcol[32];
    __shared__ float bias183[184];
    const unsigned sb = smem_u32(sm);
    const int tid = threadIdx.x, wid = tid >> 5, lane = tid & 31;
    const int q0 = blockIdx.x * 128, h = blockIdx.y, b = blockIdx.z;

    const size_t qbase = ((size_t)(b * S_LEN + q0)) * DMODEL + h * DKV;
    const size_t kbase = ((size_t)(b * S_LEN)) * DMODEL + h * DKV;

    // group 0: Q (hi+lo) + tile 0 (Kh, Kl, V)
    load_tile_f(sb + FQOFF, Qh + qbase, tid);
    load_tile_f(sb + FQOFF + FMAT, Ql + qbase, tid);
    load_tile_f(sb, Kh + kbase, tid);
    load_tile_f(sb + FMAT, Kl + kbase, tid);
    load_tile_f(sb + 2 * FMAT, Vf + kbase, tid);
    CP_COMMIT();

    if (tid < 32) tcol[tid] = tbl[tid * NHEADS + h];
    __syncthreads();
    if (tid < 183) bias183[tid] = tcol[rel_bucket(tid - 91)];

    const int u = lane & 3, g = lane >> 2;
    const int qA = q0 + wid * 16 + g;     // global q row of c0/c1
    const int qB = qA + 8;                // global q row of c2/c3

    const unsigned aoff = (unsigned)((lane & 15) * FPITCH + (lane >> 4) * 16);
    const unsigned boff = (unsigned)(((((lane >> 4) << 3) | (lane & 7)) * FPITCH)
                                     + ((lane >> 3) & 1) * 16);
    const unsigned voff = (unsigned)(((((lane >> 3) & 1) * 8 + (lane & 7)) * FPITCH)
                                     + (lane >> 4) * 16);

    unsigned aqh[4][4], aql[4][4];
    float accO[8][4];
#pragma unroll
    for (int i = 0; i < 8; i++)
#pragma unroll
        for (int j = 0; j < 4; j++) accO[i][j] = 0.0f;
    float mA = -1e30f, mB = -1e30f, lA = 0.0f, lB = 0.0f;

    for (int t = 0; t < 16; t++) {
        if (t + 1 < 16) {
            unsigned st = sb + (unsigned)(((t + 1) & 1) * FSTAGE);
            size_t kb2 = kbase + (size_t)(t + 1) * 128 * DMODEL;
            load_tile_f(st, Kh + kb2, tid);
            load_tile_f(st + FMAT, Kl + kb2, tid);
            load_tile_f(st + 2 * FMAT, Vf + kb2, tid);
            CP_COMMIT();
            CP_WAIT1();
        } else {
            CP_WAIT0();
        }
        __syncthreads();

        if (t == 0) {
#pragma unroll
            for (int c = 0; c < 4; c++) {
                unsigned qa = sb + FQOFF + (unsigned)(wid * 16 * FPITCH) + aoff
                            + (unsigned)(c * 32);
                LDMATRIX_X4(aqh[c][0], aqh[c][1], aqh[c][2], aqh[c][3], qa);
                LDMATRIX_X4(aql[c][0], aql[c][1], aql[c][2], aql[c][3], qa + FMAT);
            }
        }

        const unsigned stg = sb + (unsigned)((t & 1) * FSTAGE);

        // ---- S = Q K^T (split fp16, f32 accum) ----
        float accS[16][4];
#pragma unroll
        for (int i = 0; i < 16; i++)
#pragma unroll
            for (int j = 0; j < 4; j++) accS[i][j] = 0.0f;

#pragma unroll
        for (int c = 0; c < 4; c++) {
#pragma unroll
            for (int gg = 0; gg < 8; gg++) {
                unsigned bh0, bh1, bh2, bh3, bl0, bl1, bl2, bl3;
                unsigned ka = stg + boff + (unsigned)(gg * 16 * FPITCH + c * 32);
                LDMATRIX_X4(bh0, bh1, bh2, bh3, ka);
                LDMATRIX_X4(bl0, bl1, bl2, bl3, ka + FMAT);
                MMAF16(accS[2 * gg], aqh[c][0], aqh[c][1], aqh[c][2], aqh[c][3], bh0, bh1);
                MMAF16(accS[2 * gg + 1], aqh[c][0], aqh[c][1], aqh[c][2], aqh[c][3], bh2, bh3);
                MMAF16(accS[2 * gg], aqh[c][0], aqh[c][1], aqh[c][2], aqh[c][3], bl0, bl1);
                MMAF16(accS[2 * gg + 1], aqh[c][0], aqh[c][1], aqh[c][2], aqh[c][3], bl2, bl3);
                MMAF16(accS[2 * gg], aql[c][0], aql[c][1], aql[c][2], aql[c][3], bh0, bh1);
                MMAF16(accS[2 * gg + 1], aql[c][0], aql[c][1], aql[c][2], aql[c][3], bh2, bh3);
            }
        }

        // ---- bias + online softmax ----
        const int k0 = t * 128;
        float tmA = -1e30f, tmB = -1e30f;
#pragma unroll
        for (int s8 = 0; s8 < 16; s8++) {
            int kc = k0 + s8 * 8 + 2 * u;
            int iA0 = min(max(kc - qA, -91), 91) + 91;
            int iA1 = min(max(kc + 1 - qA, -91), 91) + 91;
            int iB0 = min(max(kc - qB, -91), 91) + 91;
            int iB1 = min(max(kc + 1 - qB, -91), 91) + 91;
            accS[s8][0] += bias183[iA0];
            accS[s8][1] += bias183[iA1];
            accS[s8][2] += bias183[iB0];
            accS[s8][3] += bias183[iB1];
            tmA = fmaxf(tmA, fmaxf(accS[s8][0], accS[s8][1]));
            tmB = fmaxf(tmB, fmaxf(accS[s8][2], accS[s8][3]));
        }
        tmA = fmaxf(tmA, __shfl_xor_sync(0xffffffffu, tmA, 1));
        tmA = fmaxf(tmA, __shfl_xor_sync(0xffffffffu, tmA, 2));
        tmB = fmaxf(tmB, __shfl_xor_sync(0xffffffffu, tmB, 1));
        tmB = fmaxf(tmB, __shfl_xor_sync(0xffffffffu, tmB, 2));

        float nmA = fmaxf(mA, tmA), scA = __expf(mA - nmA);
        float nmB = fmaxf(mB, tmB), scB = __expf(mB - nmB);
        mA = nmA; mB = nmB;

        float sA = 0.0f, sB = 0.0f;
#pragma unroll
        for (int s8 = 0; s8 < 16; s8++) {
            accS[s8][0] = __expf(accS[s8][0] - nmA);
            accS[s8][1] = __expf(accS[s8][1] - nmA);
            accS[s8][2] = __expf(accS[s8][2] - nmB);
            accS[s8][3] = __expf(accS[s8][3] - nmB);
            sA += accS[s8][0] + accS[s8][1];
            sB += accS[s8][2] + accS[s8][3];
        }
        sA += __shfl_xor_sync(0xffffffffu, sA, 1);
        sA += __shfl_xor_sync(0xffffffffu, sA, 2);
        sB += __shfl_xor_sync(0xffffffffu, sB, 1);
        sB += __shfl_xor_sync(0xffffffffu, sB, 2);
        lA = lA * scA + sA;
        lB = lB * scB + sB;

#pragma unroll
        for (int nt = 0; nt < 8; nt++) {
            accO[nt][0] *= scA; accO[nt][1] *= scA;
            accO[nt][2] *= scB; accO[nt][3] *= scB;
        }

        // ---- O += P V (fragment chaining, fp16 P & V) ----
#pragma unroll
        for (int j = 0; j < 8; j++) {
            unsigned a0 = pack2h(accS[2 * j][0], accS[2 * j][1]);
            unsigned a1 = pack2h(accS[2 * j][2], accS[2 * j][3]);
            unsigned a2 = pack2h(accS[2 * j + 1][0], accS[2 * j + 1][1]);
            unsigned a3 = pack2h(accS[2 * j + 1][2], accS[2 * j + 1][3]);
#pragma unroll
            for (int g2 = 0; g2 < 4; g2++) {
                unsigned bv0, bv1, bv2, bv3;
                unsigned va = stg + (unsigned)(2 * FMAT) + voff
                            + (unsigned)(j * 16 * FPITCH + g2 * 32);
                LDMATRIX_X4_T(bv0, bv1, bv2, bv3, va);
                MMAF16(accO[2 * g2], a0, a1, a2, a3, bv0, bv1);
                MMAF16(accO[2 * g2 + 1], a0, a1, a2, a3, bv2, bv3);
            }
        }
        __syncthreads();
    }

    // ---- epilogue: normalize, write fp16 ----
    const float iA = 1.0f / lA, iB = 1.0f / lB;
    const size_t rowA = (size_t)(b * S_LEN + qA) * DMODEL + h * DKV;
    const size_t rowB = (size_t)(b * S_LEN + qB) * DMODEL + h * DKV;
#pragma unroll
    for (int nt = 0; nt < 8; nt++) {
        int col = nt * 8 + 2 * u;
        *(unsigned*)(Oh + rowA + col) = pack2h(accO[nt][0] * iA, accO[nt][1] * iA);
        *(unsigned*)(Oh + rowB + col) = pack2h(accO[nt][2] * iB, accO[nt][3] * iB);
    }
}

// ---------------------------------------------------------------------------
extern "C" void kernel_launch(void* const* d_in, const int* in_sizes, int n_in,
                              void* d_out, int out_size) {
    const float* X   = (const float*)d_in[0];
    const float* Wq  = (const float*)d_in[1];
    const float* Wk  = (const float*)d_in[2];
    const float* Wv  = (const float*)d_in[3];
    const float* Wo  = (const float*)d_in[4];
    const float* tbl = (const float*)d_in[5];
    float* out = (float*)d_out;

    __half *xh, *xl, *wqh, *wql, *wkh, *wkl, *wvh, *wvl, *woh, *wol;
    __half *qh, *ql, *kh, *kl, *vh, *oh;
    cudaGetSymbolAddress((void**)&xh, g_xh);
    cudaGetSymbolAddress((void**)&xl, g_xl);
    cudaGetSymbolAddress((void**)&wqh, g_wqh);
    cudaGetSymbolAddress((void**)&wql, g_wql);
    cudaGetSymbolAddress((void**)&wkh, g_wkh);
    cudaGetSymbolAddress((void**)&wkl, g_wkl);
    cudaGetSymbolAddress((void**)&wvh, g_wvh);
    cudaGetSymbolAddress((void**)&wvl, g_wvl);
    cudaGetSymbolAddress((void**)&woh, g_woh);
    cudaGetSymbolAddress((void**)&wol, g_wol);
    cudaGetSymbolAddress((void**)&qh, g_qh);
    cudaGetSymbolAddress((void**)&ql, g_ql);
    cudaGetSymbolAddress((void**)&kh, g_kh);
    cudaGetSymbolAddress((void**)&kl, g_kl);
    cudaGetSymbolAddress((void**)&vh, g_vh);
    cudaGetSymbolAddress((void**)&oh, g_oh);

    // One-time side streams + events (created on the first, non-captured call).
    static cudaStream_t s2 = nullptr, s3 = nullptr, s4 = nullptr;
    static cudaEvent_t evFork = nullptr, evJoin = nullptr;
    static cudaEvent_t evConv = nullptr, evK = nullptr, evV = nullptr;
    if (s2 == nullptr) {
        cudaStreamCreateWithFlags(&s2, cudaStreamNonBlocking);
        cudaStreamCreateWithFlags(&s3, cudaStreamNonBlocking);
        cudaStreamCreateWithFlags(&s4, cudaStreamNonBlocking);
        cudaEventCreateWithFlags(&evFork, cudaEventDisableTiming);
        cudaEventCreateWithFlags(&evJoin, cudaEventDisableTiming);
        cudaEventCreateWithFlags(&evConv, cudaEventDisableTiming);
        cudaEventCreateWithFlags(&evK, cudaEventDisableTiming);
        cudaEventCreateWithFlags(&evV, cudaEventDisableTiming);
    }

    // ---- fork: pos_bias on side stream ----
    cudaEventRecord(evFork, 0);
    cudaStreamWaitEvent(s2, evFork, 0);
    {
        dim3 bg(S_LEN, NHEADS);
        bias_kernel<<<bg, 256, 0, s2>>>(tbl, out + OUT_ELEMS);
    }
    cudaEventRecord(evJoin, s2);

    // ---- conversions (main stream) ----
    conv_all<<<12288, 256>>>(X, xh, xl, Wq, wqh, wql, Wk, wkh, wkl,
                             Wv, wvh, wvl, Wo, woh, wol);
    cudaEventRecord(evConv, 0);
    cudaStreamWaitEvent(s3, evConv, 0);
    cudaStreamWaitEvent(s4, evConv, 0);

    dim3 gg(DMODEL / 128, M_ROWS / 64);       // (8, 128) = 1024 CTAs

    cudaFuncSetAttribute(gemm_h<3, 1>, cudaFuncAttributeMaxDynamicSharedMemorySize,
                         2 * 2 * (A_MATB + B_MATB));
    cudaFuncSetAttribute(gemm_h<1, 2>, cudaFuncAttributeMaxDynamicSharedMemorySize,
                         2 * (A_MATB + B_MATB));
    cudaFuncSetAttribute(gemm_h<1, 0>, cudaFuncAttributeMaxDynamicSharedMemorySize,
                         2 * (A_MATB + B_MATB));

    // Q on main stream, K on s3, V on s4 — independent, tails overlap
    gemm_h<3, 1><<<gg, 128, 2 * 2 * (A_MATB + B_MATB)>>>(xh, xl, wqh, wql,
                                                         nullptr, qh, ql,
                                                         M_ROWS, DMODEL, DMODEL);
    gemm_h<3, 1><<<gg, 128, 2 * 2 * (A_MATB + B_MATB), s3>>>(xh, xl, wkh, wkl,
                                                             nullptr, kh, kl,
                                                             M_ROWS, DMODEL, DMODEL);
    cudaEventRecord(evK, s3);
    gemm_h<1, 2><<<gg, 128, 2 * (A_MATB + B_MATB), s4>>>(xh, nullptr, wvh, nullptr,
                                                         nullptr, vh, nullptr,
                                                         M_ROWS, DMODEL, DMODEL);
    cudaEventRecord(evV, s4);

    cudaStreamWaitEvent(0, evK, 0);
    cudaStreamWaitEvent(0, evV, 0);

    // flash attention (HMMA)
    cudaFuncSetAttribute(flash_hmma, cudaFuncAttributeMaxDynamicSharedMemorySize,
                         FLASH_SMEM);
    dim3 fg(S_LEN / 128, NHEADS, BATCH);
    flash_hmma<<<fg, 256, FLASH_SMEM>>>(qh, ql, kh, kl, vh, tbl, oh);

    // output projection (single-pass fp16, f32 out)
    gemm_h<1, 0><<<gg, 128, 2 * (A_MATB + B_MATB)>>>(oh, nullptr, woh, nullptr,
                                                     out, nullptr, nullptr,
                                                     M_ROWS, DMODEL, DMODEL);

    // ---- join: pos_bias must complete before kernel_launch's work is done ----
    cudaStreamWaitEvent(0, evJoin, 0);
}

// round 8
// speedup vs baseline: 5.6004x; 1.0465x over previous
#include <cuda_runtime.h>
#include <cuda_fp16.h>
#include <math.h>

// Problem constants (fixed shapes)
#define S_LEN   2048
#define BATCH   4
#define NHEADS  16
#define DKV     64
#define DMODEL  1024
#define M_ROWS  (BATCH * S_LEN)                 // 8192
#define OUT_ELEMS  (M_ROWS * DMODEL)            // 8388608
#define BIAS_ELEMS (NHEADS * S_LEN * S_LEN)     // 67108864

// ---------------------------------------------------------------------------
// Device scratch (fp16 everywhere)
// ---------------------------------------------------------------------------
__device__ __half g_xh[M_ROWS * DMODEL];
__device__ __half g_xl[M_ROWS * DMODEL];
__device__ __half g_wqh[DMODEL * DMODEL];
__device__ __half g_wql[DMODEL * DMODEL];
__device__ __half g_wkh[DMODEL * DMODEL];
__device__ __half g_wkl[DMODEL * DMODEL];
__device__ __half g_wvh[DMODEL * DMODEL];
__device__ __half g_wvl[DMODEL * DMODEL];
__device__ __half g_woh[DMODEL * DMODEL];
__device__ __half g_wol[DMODEL * DMODEL];
__device__ __half g_qh[M_ROWS * DMODEL];
__device__ __half g_ql[M_ROWS * DMODEL];
__device__ __half g_kh[M_ROWS * DMODEL];
__device__ __half g_kl[M_ROWS * DMODEL];
__device__ __half g_vh[M_ROWS * DMODEL];
__device__ __half g_oh[M_ROWS * DMODEL];

// ---------------------------------------------------------------------------
// PTX helpers (sm_80-level only)
// ---------------------------------------------------------------------------
__device__ __forceinline__ unsigned smem_u32(const void* p) {
    unsigned a;
    asm("{ .reg .u64 t; cvta.to.shared.u64 t, %1; cvt.u32.u64 %0, t; }"
        : "=r"(a) : "l"(p));
    return a;
}

#define LDMATRIX_X4(r0, r1, r2, r3, addr)                                      \
    asm volatile("ldmatrix.sync.aligned.m8n8.x4.shared.b16 {%0,%1,%2,%3}, [%4];" \
                 : "=r"(r0), "=r"(r1), "=r"(r2), "=r"(r3) : "r"(addr))

#define LDMATRIX_X4_T(r0, r1, r2, r3, addr)                                    \
    asm volatile("ldmatrix.sync.aligned.m8n8.x4.trans.shared.b16 {%0,%1,%2,%3}, [%4];" \
                 : "=r"(r0), "=r"(r1), "=r"(r2), "=r"(r3) : "r"(addr))

#define MMAF16(d, a0, a1, a2, a3, b0, b1)                                      \
    asm volatile("mma.sync.aligned.m16n8k16.row.col.f32.f16.f16.f32 "          \
                 "{%0,%1,%2,%3},{%4,%5,%6,%7},{%8,%9},{%0,%1,%2,%3};"          \
                 : "+f"((d)[0]), "+f"((d)[1]), "+f"((d)[2]), "+f"((d)[3])      \
                 : "r"(a0), "r"(a1), "r"(a2), "r"(a3), "r"(b0), "r"(b1))

#define CP_ASYNC16(dst, src)                                                   \
    asm volatile("cp.async.cg.shared.global [%0], [%1], 16;"                   \
                 :: "r"(dst), "l"(src) : "memory")
#define CP_COMMIT() asm volatile("cp.async.commit_group;" ::: "memory")
#define CP_WAIT1()  asm volatile("cp.async.wait_group 1;" ::: "memory")
#define CP_WAIT0()  asm volatile("cp.async.wait_group 0;" ::: "memory")

__device__ __forceinline__ unsigned pack2h(float a, float b) {
    __half2 h = __floats2half2_rn(a, b);
    return *reinterpret_cast<unsigned*>(&h);
}

// ---------------------------------------------------------------------------
// Relative-position bucket (exact integer reformulation of the reference)
// ---------------------------------------------------------------------------
__device__ __forceinline__ int rel_bucket(int rel) {
    int ret = (rel > 0) ? 16 : 0;
    int rp  = (rel < 0) ? -rel : rel;
    int off;
    if (rp < 8) {
        off = rp;
    } else {
        off = 8 + (rp >= 12) + (rp >= 16) + (rp >= 23) + (rp >= 32)
                + (rp >= 46) + (rp >= 64) + (rp >= 91);
    }
    return ret + off;
}

// ---------------------------------------------------------------------------
// pos_bias writer (float4 stores) — runs on forked stream
// ---------------------------------------------------------------------------
__global__ __launch_bounds__(256) void bias_kernel(const float* __restrict__ tbl,
                                                   float* __restrict__ outb) {
    __shared__ float tcol[32];
    const int q = blockIdx.x;
    const int h = blockIdx.y;
    if (threadIdx.x < 32) tcol[threadIdx.x] = tbl[threadIdx.x * NHEADS + h];
    __syncthreads();
    float4* row = (float4*)(outb + ((size_t)h * S_LEN + q) * S_LEN);
#pragma unroll
    for (int it = 0; it < 2; it++) {
        int k4 = threadIdx.x + it * 256;
        int k = k4 * 4;
        float4 v = make_float4(tcol[rel_bucket(k - q)],
                               tcol[rel_bucket(k + 1 - q)],
                               tcol[rel_bucket(k + 2 - q)],
                               tcol[rel_bucket(k + 3 - q)]);
        row[k4] = v;
    }
}

// ---------------------------------------------------------------------------
// ALL conversions in one launch
// ---------------------------------------------------------------------------
__global__ __launch_bounds__(256) void conv_all(
    const float* __restrict__ X,  __half* __restrict__ xh,  __half* __restrict__ xl,
    const float* __restrict__ Wq, __half* __restrict__ wqh, __half* __restrict__ wql,
    const float* __restrict__ Wk, __half* __restrict__ wkh, __half* __restrict__ wkl,
    const float* __restrict__ Wv, __half* __restrict__ wvh, __half* __restrict__ wvl,
    const float* __restrict__ Wo, __half* __restrict__ woh, __half* __restrict__ wol) {
    const int tid = threadIdx.x;
    if (blockIdx.x < 8192) {
        int idx = blockIdx.x * 256 + tid;
        float4 v = ((const float4*)X)[idx];
        __half h0 = __float2half_rn(v.x), h1 = __float2half_rn(v.y);
        __half h2 = __float2half_rn(v.z), h3 = __float2half_rn(v.w);
        unsigned* H = (unsigned*)xh;
        unsigned* L = (unsigned*)xl;
        H[idx * 2]     = pack2h(v.x, v.y);
        H[idx * 2 + 1] = pack2h(v.z, v.w);
        L[idx * 2]     = pack2h(v.x - __half2float(h0), v.y - __half2float(h1));
        L[idx * 2 + 1] = pack2h(v.z - __half2float(h2), v.w - __half2float(h3));
        return;
    }
    __shared__ float t[32][33];
    const int wi = blockIdx.x - 8192;
    const float* W;
    __half *Th, *Tl;
    switch (wi >> 10) {
        case 0:  W = Wq; Th = wqh; Tl = wql; break;
        case 1:  W = Wk; Th = wkh; Tl = wkl; break;
        case 2:  W = Wv; Th = wvh; Tl = wvl; break;
        default: W = Wo; Th = woh; Tl = wol; break;
    }
    const int b  = wi & 1023;
    const int nb = (b & 31) * 32, kb = (b >> 5) * 32;
    const int tx = tid & 31, ty = tid >> 5;
#pragma unroll
    for (int r = ty; r < 32; r += 8)
        t[r][tx] = W[(size_t)(kb + r) * DMODEL + nb + tx];
    __syncthreads();
#pragma unroll
    for (int r = ty; r < 32; r += 8) {
        float v = t[tx][r];  // = W[kb+tx][nb+r]
        __half h = __float2half_rn(v);
        Th[(size_t)(nb + r) * DMODEL + kb + tx] = h;
        Tl[(size_t)(nb + r) * DMODEL + kb + tx] =
            __float2half_rn(v - __half2float(h));
    }
}

// ---------------------------------------------------------------------------
// HMMA fp16 GEMM:
//   SPLIT==3: C = AhBh + AhBl + AlBh   SPLIT==1: C = AhBh
//   OUTM: 0 -> float C; 1 -> fp16 hi/lo pair; 2 -> fp16 single
// CTA tile 128x128, BK=32, 4 warps @ 64x64, 2-stage cp.async, 2 CTAs/SM.
// PASS-MAJOR MMA ordering: all 32 accs per pass -> no same-acc RAW chains.
// Per-accumulator add order (main, +Bl, +Al per kk) is unchanged vs prior
// rounds -> bit-identical numerics.
// ---------------------------------------------------------------------------
#define ROWB 80                               // 32 fp16 (64B) + 16B pad
#define MATB (128 * ROWB)                     // 10240 B (128 rows)

template<int SPLIT, int OUTM>
__global__ __launch_bounds__(128, 2)
void gemm_h(const __half* __restrict__ Ah, const __half* __restrict__ Al,
            const __half* __restrict__ Bh, const __half* __restrict__ Bl,
            float* __restrict__ Cf, __half* __restrict__ Ch,
            __half* __restrict__ Cl, int M, int N, int K) {
    constexpr int NSP = (SPLIT == 3) ? 2 : 1;
    constexpr int STAGEB = NSP * 2 * MATB;    // [A_sp0][A_sp1?][B_sp0][B_sp1?]
    constexpr int BOFF = NSP * MATB;
    extern __shared__ char smx[];
    const unsigned sb = smem_u32(smx);
    const int tid  = threadIdx.x;
    const int wid  = tid >> 5;
    const int lane = tid & 31;
    const int m0 = blockIdx.y * 128, n0 = blockIdx.x * 128;
    const int wm = (wid & 1) * 64;
    const int wn = (wid >> 1) * 64;

    const __half* aS[2];
    const __half* bS[2];
    aS[0] = Ah + (size_t)m0 * K;
    bS[0] = Bh + (size_t)n0 * K;
    aS[1] = (SPLIT == 3) ? (Al + (size_t)m0 * K) : aS[0];
    bS[1] = (SPLIT == 3) ? (Bl + (size_t)n0 * K) : bS[0];

    const int ldrow = tid >> 2;               // 0..31
    const int ldch  = tid & 3;                // 16B chunk (4 per 64B row)

    const unsigned a_off = (unsigned)((lane & 15) * ROWB + (lane >> 4) * 16);
    const unsigned b_off = (unsigned)((((lane >> 4) << 3) + (lane & 7)) * ROWB
                                      + ((lane >> 3) & 1) * 16);

    float acc[4][8][4];
#pragma unroll
    for (int i = 0; i < 4; i++)
#pragma unroll
        for (int j = 0; j < 8; j++)
#pragma unroll
            for (int r = 0; r < 4; r++) acc[i][j][r] = 0.0f;

    const int NIT = K / 32;

    auto load_stage = [&](int s, int kit) {
        const int k0 = kit * 32;
        unsigned db = sb + (unsigned)(s * STAGEB);
#pragma unroll
        for (int sp = 0; sp < NSP; sp++) {
#pragma unroll
            for (int i = 0; i < 4; i++) {       // A: 128 rows
                int row = ldrow + i * 32;
                CP_ASYNC16(db + (unsigned)(sp * MATB + row * ROWB + ldch * 16),
                           aS[sp] + k0 + (size_t)row * K + ldch * 8);
            }
#pragma unroll
            for (int i = 0; i < 4; i++) {       // B: 128 rows
                int row = ldrow + i * 32;
                CP_ASYNC16(db + (unsigned)(BOFF + sp * MATB + row * ROWB + ldch * 16),
                           bS[sp] + k0 + (size_t)row * K + ldch * 8);
            }
        }
    };

    load_stage(0, 0);
    CP_COMMIT();

    for (int kit = 0; kit < NIT; kit++) {
        if (kit + 1 < NIT) {
            load_stage((kit + 1) & 1, kit + 1);
            CP_COMMIT();
            CP_WAIT1();
        } else {
            CP_WAIT0();
        }
        __syncthreads();

        const unsigned tb = sb + (unsigned)((kit & 1) * STAGEB);
#pragma unroll
        for (int kk = 0; kk < 32; kk += 16) {
            unsigned afr[NSP][4][4];
            unsigned bfr[NSP][4][4];
#pragma unroll
            for (int sp = 0; sp < NSP; sp++) {
#pragma unroll
                for (int mt = 0; mt < 4; mt++) {
                    unsigned ad = tb + (unsigned)(sp * MATB) + a_off
                                + (unsigned)((wm + mt * 16) * ROWB + kk * 2);
                    LDMATRIX_X4(afr[sp][mt][0], afr[sp][mt][1],
                                afr[sp][mt][2], afr[sp][mt][3], ad);
                }
#pragma unroll
                for (int nt = 0; nt < 4; nt++) {
                    unsigned bd = tb + (unsigned)(BOFF + sp * MATB) + b_off
                                + (unsigned)((wn + nt * 16) * ROWB + kk * 2);
                    LDMATRIX_X4(bfr[sp][nt][0], bfr[sp][nt][1],
                                bfr[sp][nt][2], bfr[sp][nt][3], bd);
                }
            }
            // pass 1: Ah * Bh  (32 independent accs)
#pragma unroll
            for (int mt = 0; mt < 4; mt++)
#pragma unroll
                for (int n8 = 0; n8 < 8; n8++)
                    MMAF16(acc[mt][n8], afr[0][mt][0], afr[0][mt][1],
                           afr[0][mt][2], afr[0][mt][3],
                           bfr[0][n8 >> 1][(n8 & 1) * 2],
                           bfr[0][n8 >> 1][(n8 & 1) * 2 + 1]);
            if (SPLIT == 3) {
                // pass 2: Ah * Bl
#pragma unroll
                for (int mt = 0; mt < 4; mt++)
#pragma unroll
                    for (int n8 = 0; n8 < 8; n8++)
                        MMAF16(acc[mt][n8], afr[0][mt][0], afr[0][mt][1],
                               afr[0][mt][2], afr[0][mt][3],
                               bfr[1][n8 >> 1][(n8 & 1) * 2],
                               bfr[1][n8 >> 1][(n8 & 1) * 2 + 1]);
                // pass 3: Al * Bh
#pragma unroll
                for (int mt = 0; mt < 4; mt++)
#pragma unroll
                    for (int n8 = 0; n8 < 8; n8++)
                        MMAF16(acc[mt][n8], afr[1][mt][0], afr[1][mt][1],
                               afr[1][mt][2], afr[1][mt][3],
                               bfr[0][n8 >> 1][(n8 & 1) * 2],
                               bfr[0][n8 >> 1][(n8 & 1) * 2 + 1]);
            }
        }
        __syncthreads();
    }

    // ---- epilogue ----
    const int r0 = lane >> 2, c0 = (lane & 3) * 2;
#pragma unroll
    for (int mt = 0; mt < 4; mt++) {
#pragma unroll
        for (int n8 = 0; n8 < 8; n8++) {
            int row = m0 + wm + mt * 16 + r0;
            int col = n0 + wn + n8 * 8 + c0;
            float v0 = acc[mt][n8][0], v1 = acc[mt][n8][1];
            float v2 = acc[mt][n8][2], v3 = acc[mt][n8][3];
            if (OUTM == 0) {
                float* Cp = Cf + (size_t)row * N + col;
                *(float2*)Cp = make_float2(v0, v1);
                *(float2*)(Cp + (size_t)8 * N) = make_float2(v2, v3);
            } else if (OUTM == 2) {
                *(unsigned*)(Ch + (size_t)row * N + col) = pack2h(v0, v1);
                *(unsigned*)(Ch + (size_t)(row + 8) * N + col) = pack2h(v2, v3);
            } else {
                __half h0 = __float2half_rn(v0), h1 = __float2half_rn(v1);
                __half h2 = __float2half_rn(v2), h3 = __float2half_rn(v3);
                *(unsigned*)(Ch + (size_t)row * N + col) =
                    *(unsigned*)&h0 | (*(unsigned*)&h1 << 16);
                *(unsigned*)(Ch + (size_t)(row + 8) * N + col) =
                    *(unsigned*)&h2 | (*(unsigned*)&h3 << 16);
                *(unsigned*)(Cl + (size_t)row * N + col) =
                    pack2h(v0 - __half2float(h0), v1 - __half2float(h1));
                *(unsigned*)(Cl + (size_t)(row + 8) * N + col) =
                    pack2h(v2 - __half2float(h2), v3 - __half2float(h3));
            }
        }
    }
}

// ---------------------------------------------------------------------------
// HMMA flash attention: 128q x 128k tiles, 8 warps (16 q-rows each).
// QK split-fp16 (3 MMAs), PV single fp16 via fragment chaining + ldmatrix.trans.
// QK inner loop processes 2 gg-groups at once, pass-major over 4 accs
// (same-acc gap 1 -> 3; per-acc order qh*bh, qh*bl, ql*bh preserved).
// ---------------------------------------------------------------------------
#define FPITCH 144
#define FMAT (128 * FPITCH)                   // 18432
#define FSTAGE (3 * FMAT)                     // Kh, Kl, V
#define FQOFF (2 * FSTAGE)                    // 110592
#define FLASH_SMEM (FQOFF + 2 * FMAT)         // 147456

__device__ __forceinline__ void load_tile_f(unsigned sdst, const __half* g, int tid) {
#pragma unroll
    for (int i = 0; i < 4; i++) {
        int c = tid + i * 256;
        int row = c >> 3, ch = c & 7;
        CP_ASYNC16(sdst + (unsigned)(row * FPITCH + ch * 16),
                   g + (size_t)row * DMODEL + ch * 8);
    }
}

__global__ __launch_bounds__(256, 1)
void flash_hmma(const __half* __restrict__ Qh, const __half* __restrict__ Ql,
                const __half* __restrict__ Kh, const __half* __restrict__ Kl,
                const __half* __restrict__ Vf, const float* __restrict__ tbl,
                __half* __restrict__ Oh) {
    extern __shared__ char sm[];
    __shared__ float tcol[32];
    __shared__ float bias183[184];
    const unsigned sb = smem_u32(sm);
    const int tid = threadIdx.x, wid = tid >> 5, lane = tid & 31;
    const int q0 = blockIdx.x * 128, h = blockIdx.y, b = blockIdx.z;

    const size_t qbase = ((size_t)(b * S_LEN + q0)) * DMODEL + h * DKV;
    const size_t kbase = ((size_t)(b * S_LEN)) * DMODEL + h * DKV;

    // group 0: Q (hi+lo) + tile 0 (Kh, Kl, V)
    load_tile_f(sb + FQOFF, Qh + qbase, tid);
    load_tile_f(sb + FQOFF + FMAT, Ql + qbase, tid);
    load_tile_f(sb, Kh + kbase, tid);
    load_tile_f(sb + FMAT, Kl + kbase, tid);
    load_tile_f(sb + 2 * FMAT, Vf + kbase, tid);
    CP_COMMIT();

    if (tid < 32) tcol[tid] = tbl[tid * NHEADS + h];
    __syncthreads();
    if (tid < 183) bias183[tid] = tcol[rel_bucket(tid - 91)];

    const int u = lane & 3, g = lane >> 2;
    const int qA = q0 + wid * 16 + g;     // global q row of c0/c1
    const int qB = qA + 8;                // global q row of c2/c3

    const unsigned aoff = (unsigned)((lane & 15) * FPITCH + (lane >> 4) * 16);
    const unsigned boff = (unsigned)(((((lane >> 4) << 3) | (lane & 7)) * FPITCH)
                                     + ((lane >> 3) & 1) * 16);
    const unsigned voff = (unsigned)(((((lane >> 3) & 1) * 8 + (lane & 7)) * FPITCH)
                                     + (lane >> 4) * 16);

    unsigned aqh[4][4], aql[4][4];
    float accO[8][4];
#pragma unroll
    for (int i = 0; i < 8; i++)
#pragma unroll
        for (int j = 0; j < 4; j++) accO[i][j] = 0.0f;
    float mA = -1e30f, mB = -1e30f, lA = 0.0f, lB = 0.0f;

    for (int t = 0; t < 16; t++) {
        if (t + 1 < 16) {
            unsigned st = sb + (unsigned)(((t + 1) & 1) * FSTAGE);
            size_t kb2 = kbase + (size_t)(t + 1) * 128 * DMODEL;
            load_tile_f(st, Kh + kb2, tid);
            load_tile_f(st + FMAT, Kl + kb2, tid);
            load_tile_f(st + 2 * FMAT, Vf + kb2, tid);
            CP_COMMIT();
            CP_WAIT1();
        } else {
            CP_WAIT0();
        }
        __syncthreads();

        if (t == 0) {
#pragma unroll
            for (int c = 0; c < 4; c++) {
                unsigned qa = sb + FQOFF + (unsigned)(wid * 16 * FPITCH) + aoff
                            + (unsigned)(c * 32);
                LDMATRIX_X4(aqh[c][0], aqh[c][1], aqh[c][2], aqh[c][3], qa);
                LDMATRIX_X4(aql[c][0], aql[c][1], aql[c][2], aql[c][3], qa + FMAT);
            }
        }

        const unsigned stg = sb + (unsigned)((t & 1) * FSTAGE);

        // ---- S = Q K^T (split fp16, f32 accum), 2-gg groups, pass-major ----
        float accS[16][4];
#pragma unroll
        for (int i = 0; i < 16; i++)
#pragma unroll
            for (int j = 0; j < 4; j++) accS[i][j] = 0.0f;

#pragma unroll
        for (int c = 0; c < 4; c++) {
#pragma unroll
            for (int gp = 0; gp < 4; gp++) {
                unsigned bh[8], bl[8];
#pragma unroll
                for (int e = 0; e < 2; e++) {
                    unsigned ka = stg + boff
                                + (unsigned)((gp * 2 + e) * 16 * FPITCH + c * 32);
                    LDMATRIX_X4(bh[e * 4], bh[e * 4 + 1], bh[e * 4 + 2], bh[e * 4 + 3], ka);
                    LDMATRIX_X4(bl[e * 4], bl[e * 4 + 1], bl[e * 4 + 2], bl[e * 4 + 3],
                                ka + (unsigned)FMAT);
                }
                float* s0 = accS[4 * gp];
                float* s1 = accS[4 * gp + 1];
                float* s2 = accS[4 * gp + 2];
                float* s3 = accS[4 * gp + 3];
                // pass 1: qh * kh
                MMAF16(s0, aqh[c][0], aqh[c][1], aqh[c][2], aqh[c][3], bh[0], bh[1]);
                MMAF16(s1, aqh[c][0], aqh[c][1], aqh[c][2], aqh[c][3], bh[2], bh[3]);
                MMAF16(s2, aqh[c][0], aqh[c][1], aqh[c][2], aqh[c][3], bh[4], bh[5]);
                MMAF16(s3, aqh[c][0], aqh[c][1], aqh[c][2], aqh[c][3], bh[6], bh[7]);
                // pass 2: qh * kl
                MMAF16(s0, aqh[c][0], aqh[c][1], aqh[c][2], aqh[c][3], bl[0], bl[1]);
                MMAF16(s1, aqh[c][0], aqh[c][1], aqh[c][2], aqh[c][3], bl[2], bl[3]);
                MMAF16(s2, aqh[c][0], aqh[c][1], aqh[c][2], aqh[c][3], bl[4], bl[5]);
                MMAF16(s3, aqh[c][0], aqh[c][1], aqh[c][2], aqh[c][3], bl[6], bl[7]);
                // pass 3: ql * kh
                MMAF16(s0, aql[c][0], aql[c][1], aql[c][2], aql[c][3], bh[0], bh[1]);
                MMAF16(s1, aql[c][0], aql[c][1], aql[c][2], aql[c][3], bh[2], bh[3]);
                MMAF16(s2, aql[c][0], aql[c][1], aql[c][2], aql[c][3], bh[4], bh[5]);
                MMAF16(s3, aql[c][0], aql[c][1], aql[c][2], aql[c][3], bh[6], bh[7]);
            }
        }

        // ---- bias + online softmax ----
        const int k0 = t * 128;
        float tmA = -1e30f, tmB = -1e30f;
#pragma unroll
        for (int s8 = 0; s8 < 16; s8++) {
            int kc = k0 + s8 * 8 + 2 * u;
            int iA0 = min(max(kc - qA, -91), 91) + 91;
            int iA1 = min(max(kc + 1 - qA, -91), 91) + 91;
            int iB0 = min(max(kc - qB, -91), 91) + 91;
            int iB1 = min(max(kc + 1 - qB, -91), 91) + 91;
            accS[s8][0] += bias183[iA0];
            accS[s8][1] += bias183[iA1];
            accS[s8][2] += bias183[iB0];
            accS[s8][3] += bias183[iB1];
            tmA = fmaxf(tmA, fmaxf(accS[s8][0], accS[s8][1]));
            tmB = fmaxf(tmB, fmaxf(accS[s8][2], accS[s8][3]));
        }
        tmA = fmaxf(tmA, __shfl_xor_sync(0xffffffffu, tmA, 1));
        tmA = fmaxf(tmA, __shfl_xor_sync(0xffffffffu, tmA, 2));
        tmB = fmaxf(tmB, __shfl_xor_sync(0xffffffffu, tmB, 1));
        tmB = fmaxf(tmB, __shfl_xor_sync(0xffffffffu, tmB, 2));

        float nmA = fmaxf(mA, tmA), scA = __expf(mA - nmA);
        float nmB = fmaxf(mB, tmB), scB = __expf(mB - nmB);
        mA = nmA; mB = nmB;

        float sA = 0.0f, sB = 0.0f;
#pragma unroll
        for (int s8 = 0; s8 < 16; s8++) {
            accS[s8][0] = __expf(accS[s8][0] - nmA);
            accS[s8][1] = __expf(accS[s8][1] - nmA);
            accS[s8][2] = __expf(accS[s8][2] - nmB);
            accS[s8][3] = __expf(accS[s8][3] - nmB);
            sA += accS[s8][0] + accS[s8][1];
            sB += accS[s8][2] + accS[s8][3];
        }
        sA += __shfl_xor_sync(0xffffffffu, sA, 1);
        sA += __shfl_xor_sync(0xffffffffu, sA, 2);
        sB += __shfl_xor_sync(0xffffffffu, sB, 1);
        sB += __shfl_xor_sync(0xffffffffu, sB, 2);
        lA = lA * scA + sA;
        lB = lB * scB + sB;

#pragma unroll
        for (int nt = 0; nt < 8; nt++) {
            accO[nt][0] *= scA; accO[nt][1] *= scA;
            accO[nt][2] *= scB; accO[nt][3] *= scB;
        }

        // ---- O += P V (fragment chaining, fp16 P & V) ----
#pragma unroll
        for (int j = 0; j < 8; j++) {
            unsigned a0 = pack2h(accS[2 * j][0], accS[2 * j][1]);
            unsigned a1 = pack2h(accS[2 * j][2], accS[2 * j][3]);
            unsigned a2 = pack2h(accS[2 * j + 1][0], accS[2 * j + 1][1]);
            unsigned a3 = pack2h(accS[2 * j + 1][2], accS[2 * j + 1][3]);
#pragma unroll
            for (int g2 = 0; g2 < 4; g2++) {
                unsigned bv0, bv1, bv2, bv3;
                unsigned va = stg + (unsigned)(2 * FMAT) + voff
                            + (unsigned)(j * 16 * FPITCH + g2 * 32);
                LDMATRIX_X4_T(bv0, bv1, bv2, bv3, va);
                MMAF16(accO[2 * g2], a0, a1, a2, a3, bv0, bv1);
                MMAF16(accO[2 * g2 + 1], a0, a1, a2, a3, bv2, bv3);
            }
        }
        __syncthreads();
    }

    // ---- epilogue: normalize, write fp16 ----
    const float iA = 1.0f / lA, iB = 1.0f / lB;
    const size_t rowA = (size_t)(b * S_LEN + qA) * DMODEL + h * DKV;
    const size_t rowB = (size_t)(b * S_LEN + qB) * DMODEL + h * DKV;
#pragma unroll
    for (int nt = 0; nt < 8; nt++) {
        int col = nt * 8 + 2 * u;
        *(unsigned*)(Oh + rowA + col) = pack2h(accO[nt][0] * iA, accO[nt][1] * iA);
        *(unsigned*)(Oh + rowB + col) = pack2h(accO[nt][2] * iB, accO[nt][3] * iB);
    }
}

// ---------------------------------------------------------------------------
extern "C" void kernel_launch(void* const* d_in, const int* in_sizes, int n_in,
                              void* d_out, int out_size) {
    const float* X   = (const float*)d_in[0];
    const float* Wq  = (const float*)d_in[1];
    const float* Wk  = (const float*)d_in[2];
    const float* Wv  = (const float*)d_in[3];
    const float* Wo  = (const float*)d_in[4];
    const float* tbl = (const float*)d_in[5];
    float* out = (float*)d_out;

    __half *xh, *xl, *wqh, *wql, *wkh, *wkl, *wvh, *wvl, *woh, *wol;
    __half *qh, *ql, *kh, *kl, *vh, *oh;
    cudaGetSymbolAddress((void**)&xh, g_xh);
    cudaGetSymbolAddress((void**)&xl, g_xl);
    cudaGetSymbolAddress((void**)&wqh, g_wqh);
    cudaGetSymbolAddress((void**)&wql, g_wql);
    cudaGetSymbolAddress((void**)&wkh, g_wkh);
    cudaGetSymbolAddress((void**)&wkl, g_wkl);
    cudaGetSymbolAddress((void**)&wvh, g_wvh);
    cudaGetSymbolAddress((void**)&wvl, g_wvl);
    cudaGetSymbolAddress((void**)&woh, g_woh);
    cudaGetSymbolAddress((void**)&wol, g_wol);
    cudaGetSymbolAddress((void**)&qh, g_qh);
    cudaGetSymbolAddress((void**)&ql, g_ql);
    cudaGetSymbolAddress((void**)&kh, g_kh);
    cudaGetSymbolAddress((void**)&kl, g_kl);
    cudaGetSymbolAddress((void**)&vh, g_vh);
    cudaGetSymbolAddress((void**)&oh, g_oh);

    // One-time side streams + events (created on the first, non-captured call).
    static cudaStream_t s2 = nullptr, s3 = nullptr, s4 = nullptr;
    static cudaEvent_t evFork = nullptr, evJoin = nullptr;
    static cudaEvent_t evConv = nullptr, evK = nullptr, evV = nullptr;
    if (s2 == nullptr) {
        cudaStreamCreateWithFlags(&s2, cudaStreamNonBlocking);
        cudaStreamCreateWithFlags(&s3, cudaStreamNonBlocking);
        cudaStreamCreateWithFlags(&s4, cudaStreamNonBlocking);
        cudaEventCreateWithFlags(&evFork, cudaEventDisableTiming);
        cudaEventCreateWithFlags(&evJoin, cudaEventDisableTiming);
        cudaEventCreateWithFlags(&evConv, cudaEventDisableTiming);
        cudaEventCreateWithFlags(&evK, cudaEventDisableTiming);
        cudaEventCreateWithFlags(&evV, cudaEventDisableTiming);
    }

    // ---- fork: pos_bias on side stream ----
    cudaEventRecord(evFork, 0);
    cudaStreamWaitEvent(s2, evFork, 0);
    {
        dim3 bg(S_LEN, NHEADS);
        bias_kernel<<<bg, 256, 0, s2>>>(tbl, out + OUT_ELEMS);
    }
    cudaEventRecord(evJoin, s2);

    // ---- conversions (main stream) ----
    conv_all<<<12288, 256>>>(X, xh, xl, Wq, wqh, wql, Wk, wkh, wkl,
                             Wv, wvh, wvl, Wo, woh, wol);
    cudaEventRecord(evConv, 0);
    cudaStreamWaitEvent(s3, evConv, 0);
    cudaStreamWaitEvent(s4, evConv, 0);

    dim3 gg(DMODEL / 128, M_ROWS / 128);      // (8, 64) = 512 CTAs

    cudaFuncSetAttribute(gemm_h<3, 1>, cudaFuncAttributeMaxDynamicSharedMemorySize,
                         2 * 4 * MATB);
    cudaFuncSetAttribute(gemm_h<1, 2>, cudaFuncAttributeMaxDynamicSharedMemorySize,
                         2 * 2 * MATB);
    cudaFuncSetAttribute(gemm_h<1, 0>, cudaFuncAttributeMaxDynamicSharedMemorySize,
                         2 * 2 * MATB);

    // Q on main stream, K on s3, V on s4 — independent, tails overlap
    gemm_h<3, 1><<<gg, 128, 2 * 4 * MATB>>>(xh, xl, wqh, wql,
                                            nullptr, qh, ql,
                                            M_ROWS, DMODEL, DMODEL);
    gemm_h<3, 1><<<gg, 128, 2 * 4 * MATB, s3>>>(xh, xl, wkh, wkl,
                                                nullptr, kh, kl,
                                                M_ROWS, DMODEL, DMODEL);
    cudaEventRecord(evK, s3);
    gemm_h<1, 2><<<gg, 128, 2 * 2 * MATB, s4>>>(xh, nullptr, wvh, nullptr,
                                                nullptr, vh, nullptr,
                                                M_ROWS, DMODEL, DMODEL);
    cudaEventRecord(evV, s4);

    cudaStreamWaitEvent(0, evK, 0);
    cudaStreamWaitEvent(0, evV, 0);

    // flash attention (HMMA)
    cudaFuncSetAttribute(flash_hmma, cudaFuncAttributeMaxDynamicSharedMemorySize,
                         FLASH_SMEM);
    dim3 fg(S_LEN / 128, NHEADS, BATCH);
    flash_hmma<<<fg, 256, FLASH_SMEM>>>(qh, ql, kh, kl, vh, tbl, oh);

    // output projection (single-pass fp16, f32 out)
    gemm_h<1, 0><<<gg, 128, 2 * 2 * MATB>>>(oh, nullptr, woh, nullptr,
                                            out, nullptr, nullptr,
                                            M_ROWS, DMODEL, DMODEL);

    // ---- join: pos_bias must complete before kernel_launch's work is done ----
    cudaStreamWaitEvent(0, evJoin, 0);
}